// round 2
// baseline (speedup 1.0000x reference)
#include <cuda_runtime.h>
#include <cstdint>
#include <cstddef>

#define T_DIM 2048
#define B_DIM 2
#define E_DIM 1024
#define H_DIM 16
#define HD 64
#define MROWS (T_DIM * B_DIM)      // 4096
#define NEG_INF_F (-1e24f)

// Scratch (no cudaMalloc allowed)
__device__ float g_qkv[(size_t)MROWS * 3 * E_DIM];   // 4096 x 3072
__device__ float g_attn[(size_t)MROWS * E_DIM];      // 4096 x 1024
__device__ int g_mask_mode;                          // 0=uint8,1=int32,2=float32
__device__ unsigned char g_mask[MROWS];              // canonical [T,B] mask

// ---------------------------------------------------------------------------
// Mask dtype detection: inspect first 4096 bytes (valid for any candidate
// dtype since element count is 4096).
//   int32 bools: value byte at i%4==0, bytes at i%4!=0 are all zero.
//   float32 bools: 1.0f = 00 00 80 3F -> byte 0x3F appears at i%4==3.
//   uint8 bools: 0/1 at every byte position (~half nonzero).
// ---------------------------------------------------------------------------
__global__ void mask_detect_kernel(const unsigned char* __restrict__ m)
{
    __shared__ int s_nz, s_f32;
    if (threadIdx.x == 0) { s_nz = 0; s_f32 = 0; }
    __syncthreads();
    int nz = 0, f32 = 0;
    for (int i = threadIdx.x; i < MROWS; i += 256) {
        unsigned char v = m[i];
        if ((i & 3) != 0 && v != 0) nz = 1;
        if ((i & 3) == 3 && v == 0x3F) f32 = 1;
    }
    if (nz)  atomicOr(&s_nz, 1);
    if (f32) atomicOr(&s_f32, 1);
    __syncthreads();
    if (threadIdx.x == 0)
        g_mask_mode = s_f32 ? 2 : (s_nz ? 0 : 1);
}

__global__ void mask_expand_kernel(const void* __restrict__ m)
{
    int i = blockIdx.x * 256 + threadIdx.x;
    if (i >= MROWS) return;
    int mode = g_mask_mode;
    unsigned char r;
    if (mode == 0)      r = ((const unsigned char*)m)[i] != 0;
    else if (mode == 1) r = ((const int*)m)[i] != 0;
    else                r = ((const float*)m)[i] != 0.0f;
    g_mask[i] = r;
}

// ---------------------------------------------------------------------------
// Generic C[M,N] = A[M,K] * B[N,K]^T + bias[N]   (all row-major, K-contiguous)
// BM=BN=64, BK=16, 256 threads, 4x4 micro-tile with strided mapping.
// ---------------------------------------------------------------------------
__global__ void gemm_abT_bias(const float* __restrict__ A,
                              const float* __restrict__ Bw,
                              const float* __restrict__ bias,
                              float* __restrict__ C,
                              int M, int N, int K)
{
    const int BM = 64, BN = 64, BK = 16;
    __shared__ float As[BK][BM + 1];
    __shared__ float Bs[BK][BN + 1];

    int tid = threadIdx.x;          // 0..255
    int tx = tid & 15;
    int ty = tid >> 4;
    int row0 = blockIdx.y * BM;
    int col0 = blockIdx.x * BN;

    float acc[4][4];
#pragma unroll
    for (int i = 0; i < 4; i++)
#pragma unroll
        for (int j = 0; j < 4; j++) acc[i][j] = 0.f;

    for (int k0 = 0; k0 < K; k0 += BK) {
#pragma unroll
        for (int i = tid; i < BM * BK; i += 256) {
            int m = i >> 4, k = i & 15;
            As[k][m] = A[(size_t)(row0 + m) * K + k0 + k];
        }
#pragma unroll
        for (int i = tid; i < BN * BK; i += 256) {
            int n = i >> 4, k = i & 15;
            Bs[k][n] = Bw[(size_t)(col0 + n) * K + k0 + k];
        }
        __syncthreads();

#pragma unroll
        for (int k = 0; k < BK; k++) {
            float a[4], b[4];
#pragma unroll
            for (int i = 0; i < 4; i++) a[i] = As[k][ty + 16 * i];
#pragma unroll
            for (int j = 0; j < 4; j++) b[j] = Bs[k][tx + 16 * j];
#pragma unroll
            for (int i = 0; i < 4; i++)
#pragma unroll
                for (int j = 0; j < 4; j++) acc[i][j] += a[i] * b[j];
        }
        __syncthreads();
    }

#pragma unroll
    for (int i = 0; i < 4; i++) {
        int m = row0 + ty + 16 * i;
#pragma unroll
        for (int j = 0; j < 4; j++) {
            int n = col0 + tx + 16 * j;
            C[(size_t)m * N + n] = acc[i][j] + bias[n];
        }
    }
}

// ---------------------------------------------------------------------------
// Flash attention. Grid: (T/64, H, B). 256 threads.
// qkv row = t*B + b; q at col h*64+d, k at +E, v at +2E.
// Output attn[t,b,h*64+d].
// ---------------------------------------------------------------------------
#define SROW 65
#define FLASH_SMEM (4 * 64 * SROW * (int)sizeof(float))   // 66560 B

__global__ void flash_attn_kernel(const float* __restrict__ qkv,
                                  float* __restrict__ attn_out)
{
    extern __shared__ float sm[];
    float* Qs = sm;                     // [64][SROW]
    float* Ks = Qs + 64 * SROW;
    float* Vs = Ks + 64 * SROW;
    float* Ps = Vs + 64 * SROW;

    int tid = threadIdx.x;
    int tx = tid & 15;
    int ty = tid >> 4;
    int b = blockIdx.z;
    int h = blockIdx.y;
    int q0 = blockIdx.x * 64;
    const float scaling = 0.125f;       // 64^-0.5

    // Load Q tile (scaled)
#pragma unroll
    for (int i = tid; i < 64 * 64; i += 256) {
        int r = i >> 6, d = i & 63;
        int t = q0 + r;
        Qs[r * SROW + d] =
            qkv[(size_t)(t * B_DIM + b) * (3 * E_DIM) + h * HD + d] * scaling;
    }

    float m_i[4], l_i[4], o[4][4];
#pragma unroll
    for (int i = 0; i < 4; i++) {
        m_i[i] = -3.0e38f; l_i[i] = 0.f;
#pragma unroll
        for (int j = 0; j < 4; j++) o[i][j] = 0.f;
    }
    __syncthreads();

    for (int s0 = 0; s0 < T_DIM; s0 += 64) {
        // Load K and V tiles
#pragma unroll
        for (int i = tid; i < 64 * 64; i += 256) {
            int r = i >> 6, d = i & 63;
            int t = s0 + r;
            size_t base = (size_t)(t * B_DIM + b) * (3 * E_DIM) + h * HD + d;
            Ks[r * SROW + d] = qkv[base + E_DIM];
            Vs[r * SROW + d] = qkv[base + 2 * E_DIM];
        }
        __syncthreads();

        // S = Q @ K^T  (micro 4x4, rows ty+16i, cols tx+16j)
        float s[4][4];
#pragma unroll
        for (int i = 0; i < 4; i++)
#pragma unroll
            for (int j = 0; j < 4; j++) s[i][j] = 0.f;

#pragma unroll 8
        for (int d = 0; d < 64; d++) {
            float a[4], bb[4];
#pragma unroll
            for (int i = 0; i < 4; i++) a[i] = Qs[(ty + 16 * i) * SROW + d];
#pragma unroll
            for (int j = 0; j < 4; j++) bb[j] = Ks[(tx + 16 * j) * SROW + d];
#pragma unroll
            for (int i = 0; i < 4; i++)
#pragma unroll
                for (int j = 0; j < 4; j++) s[i][j] += a[i] * bb[j];
        }

        // key padding mask (replace with NEG_INF) — canonical uint8 mask
#pragma unroll
        for (int j = 0; j < 4; j++) {
            int key = s0 + tx + 16 * j;
            if (g_mask[key * B_DIM + b]) {
#pragma unroll
                for (int i = 0; i < 4; i++) s[i][j] = NEG_INF_F;
            }
        }

        // online softmax per row (reduce across 16 tx lanes)
        float alpha[4];
#pragma unroll
        for (int i = 0; i < 4; i++) {
            float mx = fmaxf(fmaxf(s[i][0], s[i][1]), fmaxf(s[i][2], s[i][3]));
#pragma unroll
            for (int off = 8; off >= 1; off >>= 1)
                mx = fmaxf(mx, __shfl_xor_sync(0xffffffffu, mx, off, 16));
            float mnew = fmaxf(m_i[i], mx);
            alpha[i] = __expf(m_i[i] - mnew);
            float rs = 0.f;
#pragma unroll
            for (int j = 0; j < 4; j++) {
                float p = __expf(s[i][j] - mnew);
                s[i][j] = p;
                rs += p;
            }
#pragma unroll
            for (int off = 8; off >= 1; off >>= 1)
                rs += __shfl_xor_sync(0xffffffffu, rs, off, 16);
            l_i[i] = l_i[i] * alpha[i] + rs;
            m_i[i] = mnew;
        }

        // stage P to smem
#pragma unroll
        for (int i = 0; i < 4; i++)
#pragma unroll
            for (int j = 0; j < 4; j++)
                Ps[(ty + 16 * i) * SROW + tx + 16 * j] = s[i][j];
        __syncthreads();

        // O = O*alpha + P @ V
#pragma unroll
        for (int i = 0; i < 4; i++)
#pragma unroll
            for (int j = 0; j < 4; j++) o[i][j] *= alpha[i];

#pragma unroll 8
        for (int kk = 0; kk < 64; kk++) {
            float p[4], v[4];
#pragma unroll
            for (int i = 0; i < 4; i++) p[i] = Ps[(ty + 16 * i) * SROW + kk];
#pragma unroll
            for (int j = 0; j < 4; j++) v[j] = Vs[kk * SROW + tx + 16 * j];
#pragma unroll
            for (int i = 0; i < 4; i++)
#pragma unroll
                for (int j = 0; j < 4; j++) o[i][j] += p[i] * v[j];
        }
        __syncthreads();
    }

    // write normalized O
#pragma unroll
    for (int i = 0; i < 4; i++) {
        int t = q0 + ty + 16 * i;
        float inv = 1.f / l_i[i];
#pragma unroll
        for (int j = 0; j < 4; j++) {
            int d = tx + 16 * j;
            attn_out[(size_t)(t * B_DIM + b) * E_DIM + h * HD + d] = o[i][j] * inv;
        }
    }
}

// ---------------------------------------------------------------------------
extern "C" void kernel_launch(void* const* d_in, const int* in_sizes, int n_in,
                              void* d_out, int out_size)
{
    const float* x      = (const float*)d_in[0];   // [T,B,E]
    const float* w_in   = (const float*)d_in[1];   // [3E,E]
    const float* b_in   = (const float*)d_in[2];   // [3E]
    const float* w_out  = (const float*)d_in[3];   // [E,E]
    const float* b_out  = (const float*)d_in[4];   // [E]
    const void*  mask   = d_in[5];                 // [T,B] bool (unknown width)
    float* out = (float*)d_out;                    // [T,B,E]

    float* qkv_ptr = nullptr;
    float* attn_ptr = nullptr;
    cudaGetSymbolAddress((void**)&qkv_ptr, g_qkv);
    cudaGetSymbolAddress((void**)&attn_ptr, g_attn);

    cudaFuncSetAttribute(flash_attn_kernel,
                         cudaFuncAttributeMaxDynamicSharedMemorySize,
                         FLASH_SMEM);

    dim3 blk(256);

    // 0) normalize mask to uint8
    mask_detect_kernel<<<1, 256>>>((const unsigned char*)mask);
    mask_expand_kernel<<<(MROWS + 255) / 256, 256>>>(mask);

    // 1) qkv = x @ W_in^T + b_in    [4096 x 3072]
    {
        dim3 grid((3 * E_DIM) / 64, MROWS / 64);
        gemm_abT_bias<<<grid, blk>>>(x, w_in, b_in, qkv_ptr,
                                     MROWS, 3 * E_DIM, E_DIM);
    }

    // 2) flash attention -> g_attn
    {
        dim3 grid(T_DIM / 64, H_DIM, B_DIM);
        flash_attn_kernel<<<grid, blk, FLASH_SMEM>>>(qkv_ptr, attn_ptr);
    }

    // 3) out = attn @ W_out^T + b_out   [4096 x 1024]
    {
        dim3 grid(E_DIM / 64, MROWS / 64);
        gemm_abT_bias<<<grid, blk>>>(attn_ptr, w_out, b_out, out,
                                     MROWS, E_DIM, E_DIM);
    }
}

// round 4
// speedup vs baseline: 1.6143x; 1.6143x over previous
#include <cuda_runtime.h>
#include <cuda_bf16.h>
#include <cstdint>
#include <cstddef>

#define T_DIM 2048
#define B_DIM 2
#define E_DIM 1024
#define H_DIM 16
#define HD 64
#define MROWS (T_DIM * B_DIM)      // 4096
#define K_DIM 1024
#define NEG_INF_F (-1e24f)

// Scratch (no cudaMalloc allowed)
__device__ float g_qkv[(size_t)MROWS * 3 * E_DIM];   // 4096 x 3072
__device__ float g_attn[(size_t)MROWS * E_DIM];      // 4096 x 1024
__device__ int g_mask_mode;
__device__ unsigned char g_mask[MROWS];

// ===========================================================================
// Mask normalization (dtype-agnostic)
// ===========================================================================
__global__ void mask_detect_kernel(const unsigned char* __restrict__ m)
{
    __shared__ int s_nz, s_f32;
    if (threadIdx.x == 0) { s_nz = 0; s_f32 = 0; }
    __syncthreads();
    int nz = 0, f32 = 0;
    for (int i = threadIdx.x; i < MROWS; i += 256) {
        unsigned char v = m[i];
        if ((i & 3) != 0 && v != 0) nz = 1;
        if ((i & 3) == 3 && v == 0x3F) f32 = 1;
    }
    if (nz)  atomicOr(&s_nz, 1);
    if (f32) atomicOr(&s_f32, 1);
    __syncthreads();
    if (threadIdx.x == 0)
        g_mask_mode = s_f32 ? 2 : (s_nz ? 0 : 1);
}

__global__ void mask_expand_kernel(const void* __restrict__ m)
{
    int i = blockIdx.x * 256 + threadIdx.x;
    if (i >= MROWS) return;
    int mode = g_mask_mode;
    unsigned char r;
    if (mode == 0)      r = ((const unsigned char*)m)[i] != 0;
    else if (mode == 1) r = ((const int*)m)[i] != 0;
    else                r = ((const float*)m)[i] != 0.0f;
    g_mask[i] = r;
}

// ===========================================================================
// mma.sync helpers (base sm_103 — no tcgen05 available in this toolchain)
// ===========================================================================
__device__ __forceinline__ uint32_t smem_u32(const void* p) {
    uint32_t a;
    asm("{ .reg .u64 t; cvta.to.shared.u64 t, %1; cvt.u32.u64 %0, t; }"
        : "=r"(a) : "l"(p));
    return a;
}

__device__ __forceinline__ void ldmatrix_x4(uint32_t& r0, uint32_t& r1,
                                            uint32_t& r2, uint32_t& r3,
                                            uint32_t addr) {
    asm volatile("ldmatrix.sync.aligned.m8n8.x4.shared.b16 {%0,%1,%2,%3}, [%4];"
                 : "=r"(r0), "=r"(r1), "=r"(r2), "=r"(r3) : "r"(addr));
}
__device__ __forceinline__ void ldmatrix_x2(uint32_t& r0, uint32_t& r1,
                                            uint32_t addr) {
    asm volatile("ldmatrix.sync.aligned.m8n8.x2.shared.b16 {%0,%1}, [%2];"
                 : "=r"(r0), "=r"(r1) : "r"(addr));
}
__device__ __forceinline__ void mma_bf16(float* d, const uint32_t* a,
                                         const uint32_t* b) {
    asm volatile(
        "mma.sync.aligned.m16n8k16.row.col.f32.bf16.bf16.f32 "
        "{%0,%1,%2,%3}, {%4,%5,%6,%7}, {%8,%9}, {%0,%1,%2,%3};"
        : "+f"(d[0]), "+f"(d[1]), "+f"(d[2]), "+f"(d[3])
        : "r"(a[0]), "r"(a[1]), "r"(a[2]), "r"(a[3]), "r"(b[0]), "r"(b[1]));
}

// split float -> (hi, lo) bf16 pair packed as two bf162 words
__device__ __forceinline__ void split2(float x, float y,
                                       uint32_t& hi, uint32_t& lo) {
    __nv_bfloat16 hx = __float2bfloat16(x);
    __nv_bfloat16 hy = __float2bfloat16(y);
    __nv_bfloat16 lx = __float2bfloat16(x - __bfloat162float(hx));
    __nv_bfloat16 ly = __float2bfloat16(y - __bfloat162float(hy));
    __nv_bfloat162 hp = __halves2bfloat162(hx, hy);
    __nv_bfloat162 lp = __halves2bfloat162(lx, ly);
    hi = *(uint32_t*)&hp;
    lo = *(uint32_t*)&lp;
}

// ===========================================================================
// Split-bf16 HMMA GEMM: C[M,N] = A[M,1024] * Bw[N,1024]^T + bias[N]
// CTA tile 128(M) x 64(N), K-chunk 64. 8 warps: warp grid 4(m) x 2(n),
// warp tile 32x32 = 2 m-frags x 4 n-frags of m16n8k16. 3-pass hi/lo.
// smem rows padded to 72 bf16 (144 B = 36 banks -> conflict-free ldmatrix).
// ===========================================================================
#define GPAD 72
#define GA_HI 0
#define GA_LO (128 * GPAD * 2)              // 18432
#define GB_HI (2 * 128 * GPAD * 2)          // 36864
#define GB_LO (GB_HI + 64 * GPAD * 2)       // 46080
#define GS_TOTAL (GB_LO + 64 * GPAD * 2)    // 55296

__global__ __launch_bounds__(256, 2)
void gemm_mma_kernel(const float* __restrict__ A,
                     const float* __restrict__ Bw,
                     const float* __restrict__ bias,
                     float* __restrict__ C,
                     int N)
{
    extern __shared__ char sm[];
    uint32_t sbase = smem_u32(sm);
    int tid  = threadIdx.x;
    int lane = tid & 31;
    int wid  = tid >> 5;
    int warp_m = wid & 3;          // 0..3
    int warp_n = wid >> 2;         // 0..1
    int m0 = blockIdx.y * 128;
    int n0 = blockIdx.x * 64;

    float acc[2][4][4];
#pragma unroll
    for (int i = 0; i < 2; i++)
#pragma unroll
        for (int j = 0; j < 4; j++)
#pragma unroll
            for (int c = 0; c < 4; c++) acc[i][j][c] = 0.f;

    // ldmatrix source addresses (byte offsets into smem), fixed per lane
    // A: lane L -> row (L%16), col block (L/16)*8
    int a_row = lane & 15, a_cb = lane >> 4;
    // B: lane L -> row (L&7), col block ((L>>3)&1)*8  (x2 uses lanes 0..15)
    int b_row = lane & 7, b_cb = (lane >> 3) & 1;

    for (int k0 = 0; k0 < K_DIM; k0 += 64) {
        __syncthreads();
        // ---- load + split A tile (128x64) : 2048 float4, 8 per thread ----
#pragma unroll
        for (int it = 0; it < 8; it++) {
            int idx = tid + it * 256;          // 0..2047
            int row = idx >> 4;
            int cg  = idx & 15;                // float4 group
            float4 v = *(const float4*)(A + (size_t)(m0 + row) * K_DIM + k0 + cg * 4);
            uint32_t h0, l0, h1, l1;
            split2(v.x, v.y, h0, l0);
            split2(v.z, v.w, h1, l1);
            uint32_t off = (uint32_t)(row * GPAD + cg * 4) * 2;
            *(uint32_t*)(sm + GA_HI + off)     = h0;
            *(uint32_t*)(sm + GA_HI + off + 4) = h1;
            *(uint32_t*)(sm + GA_LO + off)     = l0;
            *(uint32_t*)(sm + GA_LO + off + 4) = l1;
        }
        // ---- load + split B tile (64x64) : 1024 float4, 4 per thread ----
#pragma unroll
        for (int it = 0; it < 4; it++) {
            int idx = tid + it * 256;          // 0..1023
            int row = idx >> 4;
            int cg  = idx & 15;
            float4 v = *(const float4*)(Bw + (size_t)(n0 + row) * K_DIM + k0 + cg * 4);
            uint32_t h0, l0, h1, l1;
            split2(v.x, v.y, h0, l0);
            split2(v.z, v.w, h1, l1);
            uint32_t off = (uint32_t)(row * GPAD + cg * 4) * 2;
            *(uint32_t*)(sm + GB_HI + off)     = h0;
            *(uint32_t*)(sm + GB_HI + off + 4) = h1;
            *(uint32_t*)(sm + GB_LO + off)     = l0;
            *(uint32_t*)(sm + GB_LO + off + 4) = l1;
        }
        __syncthreads();

        // ---- compute 4 k-steps of m16n8k16 ----
#pragma unroll
        for (int ks = 0; ks < 4; ks++) {
            uint32_t ahi[2][4], alo[2][4];
#pragma unroll
            for (int mf = 0; mf < 2; mf++) {
                int row = warp_m * 32 + mf * 16 + a_row;
                int col = ks * 16 + a_cb * 8;
                uint32_t addr = sbase + (uint32_t)(row * GPAD + col) * 2;
                ldmatrix_x4(ahi[mf][0], ahi[mf][1], ahi[mf][2], ahi[mf][3],
                            addr + GA_HI);
                ldmatrix_x4(alo[mf][0], alo[mf][1], alo[mf][2], alo[mf][3],
                            addr + GA_LO);
            }
            uint32_t bhi[4][2], blo[4][2];
#pragma unroll
            for (int nf = 0; nf < 4; nf++) {
                int row = warp_n * 32 + nf * 8 + b_row;
                int col = ks * 16 + b_cb * 8;
                uint32_t addr = sbase + (uint32_t)(row * GPAD + col) * 2;
                ldmatrix_x2(bhi[nf][0], bhi[nf][1], addr + GB_HI);
                ldmatrix_x2(blo[nf][0], blo[nf][1], addr + GB_LO);
            }
#pragma unroll
            for (int mf = 0; mf < 2; mf++)
#pragma unroll
                for (int nf = 0; nf < 4; nf++) {
                    mma_bf16(acc[mf][nf], ahi[mf], bhi[nf]);
                    mma_bf16(acc[mf][nf], ahi[mf], blo[nf]);
                    mma_bf16(acc[mf][nf], alo[mf], bhi[nf]);
                }
        }
    }

    // ---- epilogue: fragment -> global with bias ----
#pragma unroll
    for (int mf = 0; mf < 2; mf++) {
#pragma unroll
        for (int nf = 0; nf < 4; nf++) {
            int row = m0 + warp_m * 32 + mf * 16 + (lane >> 2);
            int col = n0 + warp_n * 32 + nf * 8 + (lane & 3) * 2;
            float b0 = bias[col], b1 = bias[col + 1];
            C[(size_t)row * N + col]           = acc[mf][nf][0] + b0;
            C[(size_t)row * N + col + 1]       = acc[mf][nf][1] + b1;
            C[(size_t)(row + 8) * N + col]     = acc[mf][nf][2] + b0;
            C[(size_t)(row + 8) * N + col + 1] = acc[mf][nf][3] + b1;
        }
    }
}

// ===========================================================================
// Flash attention (unchanged from passing round-2 version)
// ===========================================================================
#define SROW 65
#define FLASH_SMEM (4 * 64 * SROW * (int)sizeof(float))

__global__ void flash_attn_kernel(const float* __restrict__ qkv,
                                  float* __restrict__ attn_out)
{
    extern __shared__ float smf[];
    float* Qs = smf;
    float* Ks = Qs + 64 * SROW;
    float* Vs = Ks + 64 * SROW;
    float* Ps = Vs + 64 * SROW;

    int tid = threadIdx.x;
    int tx = tid & 15;
    int ty = tid >> 4;
    int b = blockIdx.z;
    int h = blockIdx.y;
    int q0 = blockIdx.x * 64;
    const float scaling = 0.125f;

#pragma unroll
    for (int i = tid; i < 64 * 64; i += 256) {
        int r = i >> 6, d = i & 63;
        int t = q0 + r;
        Qs[r * SROW + d] =
            qkv[(size_t)(t * B_DIM + b) * (3 * E_DIM) + h * HD + d] * scaling;
    }

    float m_i[4], l_i[4], o[4][4];
#pragma unroll
    for (int i = 0; i < 4; i++) {
        m_i[i] = -3.0e38f; l_i[i] = 0.f;
#pragma unroll
        for (int j = 0; j < 4; j++) o[i][j] = 0.f;
    }
    __syncthreads();

    for (int s0 = 0; s0 < T_DIM; s0 += 64) {
#pragma unroll
        for (int i = tid; i < 64 * 64; i += 256) {
            int r = i >> 6, d = i & 63;
            int t = s0 + r;
            size_t base = (size_t)(t * B_DIM + b) * (3 * E_DIM) + h * HD + d;
            Ks[r * SROW + d] = qkv[base + E_DIM];
            Vs[r * SROW + d] = qkv[base + 2 * E_DIM];
        }
        __syncthreads();

        float s[4][4];
#pragma unroll
        for (int i = 0; i < 4; i++)
#pragma unroll
            for (int j = 0; j < 4; j++) s[i][j] = 0.f;

#pragma unroll 8
        for (int d = 0; d < 64; d++) {
            float a[4], bb[4];
#pragma unroll
            for (int i = 0; i < 4; i++) a[i] = Qs[(ty + 16 * i) * SROW + d];
#pragma unroll
            for (int j = 0; j < 4; j++) bb[j] = Ks[(tx + 16 * j) * SROW + d];
#pragma unroll
            for (int i = 0; i < 4; i++)
#pragma unroll
                for (int j = 0; j < 4; j++) s[i][j] += a[i] * bb[j];
        }

#pragma unroll
        for (int j = 0; j < 4; j++) {
            int key = s0 + tx + 16 * j;
            if (g_mask[key * B_DIM + b]) {
#pragma unroll
                for (int i = 0; i < 4; i++) s[i][j] = NEG_INF_F;
            }
        }

        float alpha[4];
#pragma unroll
        for (int i = 0; i < 4; i++) {
            float mx = fmaxf(fmaxf(s[i][0], s[i][1]), fmaxf(s[i][2], s[i][3]));
#pragma unroll
            for (int off = 8; off >= 1; off >>= 1)
                mx = fmaxf(mx, __shfl_xor_sync(0xffffffffu, mx, off, 16));
            float mnew = fmaxf(m_i[i], mx);
            alpha[i] = __expf(m_i[i] - mnew);
            float rs = 0.f;
#pragma unroll
            for (int j = 0; j < 4; j++) {
                float p = __expf(s[i][j] - mnew);
                s[i][j] = p;
                rs += p;
            }
#pragma unroll
            for (int off = 8; off >= 1; off >>= 1)
                rs += __shfl_xor_sync(0xffffffffu, rs, off, 16);
            l_i[i] = l_i[i] * alpha[i] + rs;
            m_i[i] = mnew;
        }

#pragma unroll
        for (int i = 0; i < 4; i++)
#pragma unroll
            for (int j = 0; j < 4; j++)
                Ps[(ty + 16 * i) * SROW + tx + 16 * j] = s[i][j];
        __syncthreads();

#pragma unroll
        for (int i = 0; i < 4; i++)
#pragma unroll
            for (int j = 0; j < 4; j++) o[i][j] *= alpha[i];

#pragma unroll 8
        for (int kk = 0; kk < 64; kk++) {
            float p[4], v[4];
#pragma unroll
            for (int i = 0; i < 4; i++) p[i] = Ps[(ty + 16 * i) * SROW + kk];
#pragma unroll
            for (int j = 0; j < 4; j++) v[j] = Vs[kk * SROW + tx + 16 * j];
#pragma unroll
            for (int i = 0; i < 4; i++)
#pragma unroll
                for (int j = 0; j < 4; j++) o[i][j] += p[i] * v[j];
        }
        __syncthreads();
    }

#pragma unroll
    for (int i = 0; i < 4; i++) {
        int t = q0 + ty + 16 * i;
        float inv = 1.f / l_i[i];
#pragma unroll
        for (int j = 0; j < 4; j++) {
            int d = tx + 16 * j;
            attn_out[(size_t)(t * B_DIM + b) * E_DIM + h * HD + d] = o[i][j] * inv;
        }
    }
}

// ===========================================================================
extern "C" void kernel_launch(void* const* d_in, const int* in_sizes, int n_in,
                              void* d_out, int out_size)
{
    const float* x      = (const float*)d_in[0];
    const float* w_in   = (const float*)d_in[1];
    const float* b_in   = (const float*)d_in[2];
    const float* w_out  = (const float*)d_in[3];
    const float* b_out  = (const float*)d_in[4];
    const void*  mask   = d_in[5];
    float* out = (float*)d_out;

    float* qkv_ptr = nullptr;
    float* attn_ptr = nullptr;
    cudaGetSymbolAddress((void**)&qkv_ptr, g_qkv);
    cudaGetSymbolAddress((void**)&attn_ptr, g_attn);

    cudaFuncSetAttribute(flash_attn_kernel,
                         cudaFuncAttributeMaxDynamicSharedMemorySize, FLASH_SMEM);
    cudaFuncSetAttribute(gemm_mma_kernel,
                         cudaFuncAttributeMaxDynamicSharedMemorySize, GS_TOTAL);

    // 0) normalize mask
    mask_detect_kernel<<<1, 256>>>((const unsigned char*)mask);
    mask_expand_kernel<<<(MROWS + 255) / 256, 256>>>(mask);

    // 1) qkv = x @ W_in^T + b_in   [4096 x 3072]
    {
        dim3 grid((3 * E_DIM) / 64, MROWS / 128);
        gemm_mma_kernel<<<grid, 256, GS_TOTAL>>>(x, w_in, b_in, qkv_ptr, 3 * E_DIM);
    }

    // 2) flash attention
    {
        dim3 grid(T_DIM / 64, H_DIM, B_DIM);
        flash_attn_kernel<<<grid, 256, FLASH_SMEM>>>(qkv_ptr, attn_ptr);
    }

    // 3) out = attn @ W_out^T + b_out   [4096 x 1024]
    {
        dim3 grid(E_DIM / 64, MROWS / 128);
        gemm_mma_kernel<<<grid, 256, GS_TOTAL>>>(attn_ptr, w_out, b_out, out, E_DIM);
    }
}

// round 5
// speedup vs baseline: 3.4214x; 2.1194x over previous
#include <cuda_runtime.h>
#include <cuda_bf16.h>
#include <cstdint>
#include <cstddef>

#define T_DIM 2048
#define B_DIM 2
#define E_DIM 1024
#define H_DIM 16
#define HD 64
#define MROWS (T_DIM * B_DIM)      // 4096
#define K_DIM 1024
#define NEG_INF_F (-1e24f)

// Scratch (no cudaMalloc allowed)
__device__ float g_qkv[(size_t)MROWS * 3 * E_DIM];   // 4096 x 3072
__device__ float g_attn[(size_t)MROWS * E_DIM];      // 4096 x 1024
__device__ int g_mask_mode;
__device__ unsigned char g_mask[MROWS];

// ===========================================================================
// Mask normalization (dtype-agnostic)
// ===========================================================================
__global__ void mask_detect_kernel(const unsigned char* __restrict__ m)
{
    __shared__ int s_nz, s_f32;
    if (threadIdx.x == 0) { s_nz = 0; s_f32 = 0; }
    __syncthreads();
    int nz = 0, f32 = 0;
    for (int i = threadIdx.x; i < MROWS; i += 256) {
        unsigned char v = m[i];
        if ((i & 3) != 0 && v != 0) nz = 1;
        if ((i & 3) == 3 && v == 0x3F) f32 = 1;
    }
    if (nz)  atomicOr(&s_nz, 1);
    if (f32) atomicOr(&s_f32, 1);
    __syncthreads();
    if (threadIdx.x == 0)
        g_mask_mode = s_f32 ? 2 : (s_nz ? 0 : 1);
}

__global__ void mask_expand_kernel(const void* __restrict__ m)
{
    int i = blockIdx.x * 256 + threadIdx.x;
    if (i >= MROWS) return;
    int mode = g_mask_mode;
    unsigned char r;
    if (mode == 0)      r = ((const unsigned char*)m)[i] != 0;
    else if (mode == 1) r = ((const int*)m)[i] != 0;
    else                r = ((const float*)m)[i] != 0.0f;
    g_mask[i] = r;
}

// ===========================================================================
// mma.sync helpers (base sm_103 — no tcgen05 in this toolchain)
// ===========================================================================
__device__ __forceinline__ uint32_t smem_u32(const void* p) {
    uint32_t a;
    asm("{ .reg .u64 t; cvta.to.shared.u64 t, %1; cvt.u32.u64 %0, t; }"
        : "=r"(a) : "l"(p));
    return a;
}

__device__ __forceinline__ void ldmatrix_x4(uint32_t& r0, uint32_t& r1,
                                            uint32_t& r2, uint32_t& r3,
                                            uint32_t addr) {
    asm volatile("ldmatrix.sync.aligned.m8n8.x4.shared.b16 {%0,%1,%2,%3}, [%4];"
                 : "=r"(r0), "=r"(r1), "=r"(r2), "=r"(r3) : "r"(addr));
}
__device__ __forceinline__ void ldmatrix_x2(uint32_t& r0, uint32_t& r1,
                                            uint32_t addr) {
    asm volatile("ldmatrix.sync.aligned.m8n8.x2.shared.b16 {%0,%1}, [%2];"
                 : "=r"(r0), "=r"(r1) : "r"(addr));
}
__device__ __forceinline__ void ldmatrix_x2_trans(uint32_t& r0, uint32_t& r1,
                                                  uint32_t addr) {
    asm volatile("ldmatrix.sync.aligned.m8n8.x2.trans.shared.b16 {%0,%1}, [%2];"
                 : "=r"(r0), "=r"(r1) : "r"(addr));
}
__device__ __forceinline__ void mma_bf16(float* d, const uint32_t* a,
                                         const uint32_t* b) {
    asm volatile(
        "mma.sync.aligned.m16n8k16.row.col.f32.bf16.bf16.f32 "
        "{%0,%1,%2,%3}, {%4,%5,%6,%7}, {%8,%9}, {%0,%1,%2,%3};"
        : "+f"(d[0]), "+f"(d[1]), "+f"(d[2]), "+f"(d[3])
        : "r"(a[0]), "r"(a[1]), "r"(a[2]), "r"(a[3]), "r"(b[0]), "r"(b[1]));
}

// split (x,y) -> packed bf16x2 hi and lo words
__device__ __forceinline__ void split2(float x, float y,
                                       uint32_t& hi, uint32_t& lo) {
    __nv_bfloat16 hx = __float2bfloat16(x);
    __nv_bfloat16 hy = __float2bfloat16(y);
    __nv_bfloat16 lx = __float2bfloat16(x - __bfloat162float(hx));
    __nv_bfloat16 ly = __float2bfloat16(y - __bfloat162float(hy));
    __nv_bfloat162 hp = __halves2bfloat162(hx, hy);
    __nv_bfloat162 lp = __halves2bfloat162(lx, ly);
    hi = *(uint32_t*)&hp;
    lo = *(uint32_t*)&lp;
}

// ===========================================================================
// Split-bf16 HMMA GEMM: C[M,N] = A[M,1024] * Bw[N,1024]^T + bias[N]
// (unchanged from round-4 passing version)
// ===========================================================================
#define GPAD 72
#define GA_HI 0
#define GA_LO (128 * GPAD * 2)
#define GB_HI (2 * 128 * GPAD * 2)
#define GB_LO (GB_HI + 64 * GPAD * 2)
#define GS_TOTAL (GB_LO + 64 * GPAD * 2)

__global__ __launch_bounds__(256, 2)
void gemm_mma_kernel(const float* __restrict__ A,
                     const float* __restrict__ Bw,
                     const float* __restrict__ bias,
                     float* __restrict__ C,
                     int N)
{
    extern __shared__ char sm[];
    uint32_t sbase = smem_u32(sm);
    int tid  = threadIdx.x;
    int lane = tid & 31;
    int wid  = tid >> 5;
    int warp_m = wid & 3;
    int warp_n = wid >> 2;
    int m0 = blockIdx.y * 128;
    int n0 = blockIdx.x * 64;

    float acc[2][4][4];
#pragma unroll
    for (int i = 0; i < 2; i++)
#pragma unroll
        for (int j = 0; j < 4; j++)
#pragma unroll
            for (int c = 0; c < 4; c++) acc[i][j][c] = 0.f;

    int a_row = lane & 15, a_cb = lane >> 4;
    int b_row = lane & 7, b_cb = (lane >> 3) & 1;

    for (int k0 = 0; k0 < K_DIM; k0 += 64) {
        __syncthreads();
#pragma unroll
        for (int it = 0; it < 8; it++) {
            int idx = tid + it * 256;
            int row = idx >> 4;
            int cg  = idx & 15;
            float4 v = *(const float4*)(A + (size_t)(m0 + row) * K_DIM + k0 + cg * 4);
            uint32_t h0, l0, h1, l1;
            split2(v.x, v.y, h0, l0);
            split2(v.z, v.w, h1, l1);
            uint32_t off = (uint32_t)(row * GPAD + cg * 4) * 2;
            *(uint32_t*)(sm + GA_HI + off)     = h0;
            *(uint32_t*)(sm + GA_HI + off + 4) = h1;
            *(uint32_t*)(sm + GA_LO + off)     = l0;
            *(uint32_t*)(sm + GA_LO + off + 4) = l1;
        }
#pragma unroll
        for (int it = 0; it < 4; it++) {
            int idx = tid + it * 256;
            int row = idx >> 4;
            int cg  = idx & 15;
            float4 v = *(const float4*)(Bw + (size_t)(n0 + row) * K_DIM + k0 + cg * 4);
            uint32_t h0, l0, h1, l1;
            split2(v.x, v.y, h0, l0);
            split2(v.z, v.w, h1, l1);
            uint32_t off = (uint32_t)(row * GPAD + cg * 4) * 2;
            *(uint32_t*)(sm + GB_HI + off)     = h0;
            *(uint32_t*)(sm + GB_HI + off + 4) = h1;
            *(uint32_t*)(sm + GB_LO + off)     = l0;
            *(uint32_t*)(sm + GB_LO + off + 4) = l1;
        }
        __syncthreads();

#pragma unroll
        for (int ks = 0; ks < 4; ks++) {
            uint32_t ahi[2][4], alo[2][4];
#pragma unroll
            for (int mf = 0; mf < 2; mf++) {
                int row = warp_m * 32 + mf * 16 + a_row;
                int col = ks * 16 + a_cb * 8;
                uint32_t addr = sbase + (uint32_t)(row * GPAD + col) * 2;
                ldmatrix_x4(ahi[mf][0], ahi[mf][1], ahi[mf][2], ahi[mf][3],
                            addr + GA_HI);
                ldmatrix_x4(alo[mf][0], alo[mf][1], alo[mf][2], alo[mf][3],
                            addr + GA_LO);
            }
            uint32_t bhi[4][2], blo[4][2];
#pragma unroll
            for (int nf = 0; nf < 4; nf++) {
                int row = warp_n * 32 + nf * 8 + b_row;
                int col = ks * 16 + b_cb * 8;
                uint32_t addr = sbase + (uint32_t)(row * GPAD + col) * 2;
                ldmatrix_x2(bhi[nf][0], bhi[nf][1], addr + GB_HI);
                ldmatrix_x2(blo[nf][0], blo[nf][1], addr + GB_LO);
            }
#pragma unroll
            for (int mf = 0; mf < 2; mf++)
#pragma unroll
                for (int nf = 0; nf < 4; nf++) {
                    mma_bf16(acc[mf][nf], ahi[mf], bhi[nf]);
                    mma_bf16(acc[mf][nf], ahi[mf], blo[nf]);
                    mma_bf16(acc[mf][nf], alo[mf], bhi[nf]);
                }
        }
    }

#pragma unroll
    for (int mf = 0; mf < 2; mf++) {
#pragma unroll
        for (int nf = 0; nf < 4; nf++) {
            int row = m0 + warp_m * 32 + mf * 16 + (lane >> 2);
            int col = n0 + warp_n * 32 + nf * 8 + (lane & 3) * 2;
            float b0 = bias[col], b1 = bias[col + 1];
            C[(size_t)row * N + col]           = acc[mf][nf][0] + b0;
            C[(size_t)row * N + col + 1]       = acc[mf][nf][1] + b1;
            C[(size_t)(row + 8) * N + col]     = acc[mf][nf][2] + b0;
            C[(size_t)(row + 8) * N + col + 1] = acc[mf][nf][3] + b1;
        }
    }
}

// ===========================================================================
// Flash attention with mma.sync split-bf16 (3-pass QK^T and 3-pass P.V)
// Grid: (T/128, H, B), 256 threads = 8 warps, each warp owns 16 q-rows.
// ===========================================================================
#define FPAD 72
#define FQ_HI 0
#define FQ_LO (128 * FPAD * 2)             // 18432
#define FK_HI (2 * 128 * FPAD * 2)         // 36864
#define FK_LO (FK_HI + 64 * FPAD * 2)      // 46080
#define FV_HI (FK_LO + 64 * FPAD * 2)      // 55296
#define FV_LO (FV_HI + 64 * FPAD * 2)      // 64512
#define FMSK  (FV_LO + 64 * FPAD * 2)      // 73728
#define FS_TOTAL (FMSK + 64 * 4)           // 73984

__global__ __launch_bounds__(256, 2)
void flash_mma_kernel(const float* __restrict__ qkv,
                      float* __restrict__ attn_out)
{
    extern __shared__ char sm[];
    uint32_t sbase = smem_u32(sm);
    float* msk = (float*)(sm + FMSK);
    int tid = threadIdx.x;
    int lane = tid & 31;
    int w = tid >> 5;
    int b = blockIdx.z;
    int h = blockIdx.y;
    int q0 = blockIdx.x * 128;

    // ---- load Q tile (128x64), scale by 0.125, split hi/lo ----
#pragma unroll
    for (int it = 0; it < 8; it++) {
        int idx = tid + it * 256;
        int row = idx >> 4, cg = idx & 15;
        int t = q0 + row;
        float4 v = *(const float4*)(qkv + (size_t)(t * 2 + b) * 3072 + h * 64 + cg * 4);
        v.x *= 0.125f; v.y *= 0.125f; v.z *= 0.125f; v.w *= 0.125f;
        uint32_t h0, l0, h1, l1;
        split2(v.x, v.y, h0, l0);
        split2(v.z, v.w, h1, l1);
        uint32_t off = (uint32_t)(row * FPAD + cg * 4) * 2;
        *(uint32_t*)(sm + FQ_HI + off)     = h0;
        *(uint32_t*)(sm + FQ_HI + off + 4) = h1;
        *(uint32_t*)(sm + FQ_LO + off)     = l0;
        *(uint32_t*)(sm + FQ_LO + off + 4) = l1;
    }

    float m1 = -3.0e38f, m2 = -3.0e38f, l1 = 0.f, l2 = 0.f;
    float o[8][4];
#pragma unroll
    for (int nf = 0; nf < 8; nf++)
#pragma unroll
        for (int c = 0; c < 4; c++) o[nf][c] = 0.f;

    int a_row = lane & 15, a_cb = lane >> 4;
    int b_row = lane & 7,  b_cb = (lane >> 3) & 1;
    int qrow0 = w * 16;

    for (int s0 = 0; s0 < T_DIM; s0 += 64) {
        __syncthreads();   // protect prior-iteration K/V reads (and Q stores, iter 0)
        // ---- load K and V tiles (64x64 each), split hi/lo ----
#pragma unroll
        for (int it = 0; it < 4; it++) {
            int idx = tid + it * 256;
            int row = idx >> 4, cg = idx & 15;
            int t = s0 + row;
            const float* base = qkv + (size_t)(t * 2 + b) * 3072 + h * 64 + cg * 4;
            float4 kv = *(const float4*)(base + E_DIM);
            float4 vv = *(const float4*)(base + 2 * E_DIM);
            uint32_t off = (uint32_t)(row * FPAD + cg * 4) * 2;
            uint32_t h0, l0, h1, l1;
            split2(kv.x, kv.y, h0, l0);
            split2(kv.z, kv.w, h1, l1);
            *(uint32_t*)(sm + FK_HI + off)     = h0;
            *(uint32_t*)(sm + FK_HI + off + 4) = h1;
            *(uint32_t*)(sm + FK_LO + off)     = l0;
            *(uint32_t*)(sm + FK_LO + off + 4) = l1;
            split2(vv.x, vv.y, h0, l0);
            split2(vv.z, vv.w, h1, l1);
            *(uint32_t*)(sm + FV_HI + off)     = h0;
            *(uint32_t*)(sm + FV_HI + off + 4) = h1;
            *(uint32_t*)(sm + FV_LO + off)     = l0;
            *(uint32_t*)(sm + FV_LO + off + 4) = l1;
        }
        if (tid < 64)
            msk[tid] = g_mask[(s0 + tid) * B_DIM + b] ? NEG_INF_F : 0.f;
        __syncthreads();

        // ---- S = Q K^T (3-pass split), warp computes 16x64 ----
        float acc[8][4];
#pragma unroll
        for (int nf = 0; nf < 8; nf++)
#pragma unroll
            for (int c = 0; c < 4; c++) acc[nf][c] = 0.f;

#pragma unroll
        for (int kf = 0; kf < 4; kf++) {
            uint32_t qhi[4], qlo[4];
            {
                int row = qrow0 + a_row;
                int col = kf * 16 + a_cb * 8;
                uint32_t addr = sbase + (uint32_t)(row * FPAD + col) * 2;
                ldmatrix_x4(qhi[0], qhi[1], qhi[2], qhi[3], addr + FQ_HI);
                ldmatrix_x4(qlo[0], qlo[1], qlo[2], qlo[3], addr + FQ_LO);
            }
#pragma unroll
            for (int nf = 0; nf < 8; nf++) {
                uint32_t khi[2], klo[2];
                int row = nf * 8 + b_row;
                int col = kf * 16 + b_cb * 8;
                uint32_t addr = sbase + (uint32_t)(row * FPAD + col) * 2;
                ldmatrix_x2(khi[0], khi[1], addr + FK_HI);
                ldmatrix_x2(klo[0], klo[1], addr + FK_LO);
                mma_bf16(acc[nf], qhi, khi);
                mma_bf16(acc[nf], qhi, klo);
                mma_bf16(acc[nf], qlo, khi);
            }
        }

        // ---- mask add ----
#pragma unroll
        for (int nf = 0; nf < 8; nf++) {
            float2 mk = *(float2*)&msk[nf * 8 + (lane & 3) * 2];
            acc[nf][0] += mk.x; acc[nf][1] += mk.y;
            acc[nf][2] += mk.x; acc[nf][3] += mk.y;
        }

        // ---- online softmax (rows r1 = lane>>2, r2 = r1+8) ----
        float mx1 = -3.0e38f, mx2 = -3.0e38f;
#pragma unroll
        for (int nf = 0; nf < 8; nf++) {
            mx1 = fmaxf(mx1, fmaxf(acc[nf][0], acc[nf][1]));
            mx2 = fmaxf(mx2, fmaxf(acc[nf][2], acc[nf][3]));
        }
        mx1 = fmaxf(mx1, __shfl_xor_sync(0xffffffffu, mx1, 1));
        mx1 = fmaxf(mx1, __shfl_xor_sync(0xffffffffu, mx1, 2));
        mx2 = fmaxf(mx2, __shfl_xor_sync(0xffffffffu, mx2, 1));
        mx2 = fmaxf(mx2, __shfl_xor_sync(0xffffffffu, mx2, 2));

        float mn1 = fmaxf(m1, mx1);
        float mn2 = fmaxf(m2, mx2);
        float al1 = __expf(m1 - mn1);
        float al2 = __expf(m2 - mn2);
        float rs1 = 0.f, rs2 = 0.f;
#pragma unroll
        for (int nf = 0; nf < 8; nf++) {
            acc[nf][0] = __expf(acc[nf][0] - mn1);
            acc[nf][1] = __expf(acc[nf][1] - mn1);
            acc[nf][2] = __expf(acc[nf][2] - mn2);
            acc[nf][3] = __expf(acc[nf][3] - mn2);
            rs1 += acc[nf][0] + acc[nf][1];
            rs2 += acc[nf][2] + acc[nf][3];
        }
        rs1 += __shfl_xor_sync(0xffffffffu, rs1, 1);
        rs1 += __shfl_xor_sync(0xffffffffu, rs1, 2);
        rs2 += __shfl_xor_sync(0xffffffffu, rs2, 1);
        rs2 += __shfl_xor_sync(0xffffffffu, rs2, 2);
        l1 = l1 * al1 + rs1;
        l2 = l2 * al2 + rs2;
        m1 = mn1; m2 = mn2;

        // ---- rescale O ----
#pragma unroll
        for (int nf = 0; nf < 8; nf++) {
            o[nf][0] *= al1; o[nf][1] *= al1;
            o[nf][2] *= al2; o[nf][3] *= al2;
        }

        // ---- O += P V (3-pass split). P a-frags built in registers ----
#pragma unroll
        for (int kf = 0; kf < 4; kf++) {
            uint32_t phi[4], plo[4];
            split2(acc[2 * kf][0],     acc[2 * kf][1],     phi[0], plo[0]);
            split2(acc[2 * kf][2],     acc[2 * kf][3],     phi[1], plo[1]);
            split2(acc[2 * kf + 1][0], acc[2 * kf + 1][1], phi[2], plo[2]);
            split2(acc[2 * kf + 1][2], acc[2 * kf + 1][3], phi[3], plo[3]);
#pragma unroll
            for (int nf = 0; nf < 8; nf++) {
                uint32_t vhi[2], vlo[2];
                int row = kf * 16 + (lane & 15);
                int col = nf * 8;
                uint32_t addr = sbase + (uint32_t)(row * FPAD + col) * 2;
                ldmatrix_x2_trans(vhi[0], vhi[1], addr + FV_HI);
                ldmatrix_x2_trans(vlo[0], vlo[1], addr + FV_LO);
                mma_bf16(o[nf], phi, vhi);
                mma_bf16(o[nf], phi, vlo);
                mma_bf16(o[nf], plo, vhi);
            }
        }
    }

    // ---- epilogue: normalize and write ----
    float inv1 = 1.f / l1;
    float inv2 = 1.f / l2;
    int t1 = q0 + qrow0 + (lane >> 2);
    int t2 = t1 + 8;
#pragma unroll
    for (int nf = 0; nf < 8; nf++) {
        int d = h * 64 + nf * 8 + (lane & 3) * 2;
        size_t r1 = (size_t)(t1 * 2 + b) * E_DIM + d;
        size_t r2 = (size_t)(t2 * 2 + b) * E_DIM + d;
        attn_out[r1]     = o[nf][0] * inv1;
        attn_out[r1 + 1] = o[nf][1] * inv1;
        attn_out[r2]     = o[nf][2] * inv2;
        attn_out[r2 + 1] = o[nf][3] * inv2;
    }
}

// ===========================================================================
extern "C" void kernel_launch(void* const* d_in, const int* in_sizes, int n_in,
                              void* d_out, int out_size)
{
    const float* x      = (const float*)d_in[0];
    const float* w_in   = (const float*)d_in[1];
    const float* b_in   = (const float*)d_in[2];
    const float* w_out  = (const float*)d_in[3];
    const float* b_out  = (const float*)d_in[4];
    const void*  mask   = d_in[5];
    float* out = (float*)d_out;

    float* qkv_ptr = nullptr;
    float* attn_ptr = nullptr;
    cudaGetSymbolAddress((void**)&qkv_ptr, g_qkv);
    cudaGetSymbolAddress((void**)&attn_ptr, g_attn);

    cudaFuncSetAttribute(flash_mma_kernel,
                         cudaFuncAttributeMaxDynamicSharedMemorySize, FS_TOTAL);
    cudaFuncSetAttribute(gemm_mma_kernel,
                         cudaFuncAttributeMaxDynamicSharedMemorySize, GS_TOTAL);

    // 0) normalize mask
    mask_detect_kernel<<<1, 256>>>((const unsigned char*)mask);
    mask_expand_kernel<<<(MROWS + 255) / 256, 256>>>(mask);

    // 1) qkv = x @ W_in^T + b_in   [4096 x 3072]
    {
        dim3 grid((3 * E_DIM) / 64, MROWS / 128);
        gemm_mma_kernel<<<grid, 256, GS_TOTAL>>>(x, w_in, b_in, qkv_ptr, 3 * E_DIM);
    }

    // 2) flash attention (tensor-core)
    {
        dim3 grid(T_DIM / 128, H_DIM, B_DIM);
        flash_mma_kernel<<<grid, 256, FS_TOTAL>>>(qkv_ptr, attn_ptr);
    }

    // 3) out = attn @ W_out^T + b_out   [4096 x 1024]
    {
        dim3 grid(E_DIM / 64, MROWS / 128);
        gemm_mma_kernel<<<grid, 256, GS_TOTAL>>>(attn_ptr, w_out, b_out, out, E_DIM);
    }
}

// round 6
// speedup vs baseline: 3.7125x; 1.0851x over previous
#include <cuda_runtime.h>
#include <cuda_bf16.h>
#include <cstdint>
#include <cstddef>

#define T_DIM 2048
#define B_DIM 2
#define E_DIM 1024
#define H_DIM 16
#define MROWS (T_DIM * B_DIM)      // 4096
#define K_DIM 1024
#define NEG_INF_F (-1e24f)

// ---------------------------------------------------------------------------
// Scratch (no cudaMalloc allowed) — all bf16 hi/lo split pairs
// ---------------------------------------------------------------------------
__device__ __nv_bfloat16 g_x_hi[(size_t)MROWS * E_DIM];
__device__ __nv_bfloat16 g_x_lo[(size_t)MROWS * E_DIM];
__device__ __nv_bfloat16 g_win_hi[(size_t)3 * E_DIM * E_DIM];
__device__ __nv_bfloat16 g_win_lo[(size_t)3 * E_DIM * E_DIM];
__device__ __nv_bfloat16 g_wout_hi[(size_t)E_DIM * E_DIM];
__device__ __nv_bfloat16 g_wout_lo[(size_t)E_DIM * E_DIM];
__device__ __nv_bfloat16 g_qkv_hi[(size_t)MROWS * 3 * E_DIM];
__device__ __nv_bfloat16 g_qkv_lo[(size_t)MROWS * 3 * E_DIM];
__device__ __nv_bfloat16 g_attn_hi[(size_t)MROWS * E_DIM];
__device__ __nv_bfloat16 g_attn_lo[(size_t)MROWS * E_DIM];
__device__ int g_mask_mode;
__device__ unsigned char g_mask[MROWS];

// ===========================================================================
// PTX helpers (base sm_103 only: mma.sync / ldmatrix / cp.async)
// ===========================================================================
__device__ __forceinline__ uint32_t smem_u32(const void* p) {
    uint32_t a;
    asm("{ .reg .u64 t; cvta.to.shared.u64 t, %1; cvt.u32.u64 %0, t; }"
        : "=r"(a) : "l"(p));
    return a;
}
__device__ __forceinline__ void ldmatrix_x4(uint32_t& r0, uint32_t& r1,
                                            uint32_t& r2, uint32_t& r3,
                                            uint32_t addr) {
    asm volatile("ldmatrix.sync.aligned.m8n8.x4.shared.b16 {%0,%1,%2,%3}, [%4];"
                 : "=r"(r0), "=r"(r1), "=r"(r2), "=r"(r3) : "r"(addr));
}
__device__ __forceinline__ void ldmatrix_x4_trans(uint32_t& r0, uint32_t& r1,
                                                  uint32_t& r2, uint32_t& r3,
                                                  uint32_t addr) {
    asm volatile("ldmatrix.sync.aligned.m8n8.x4.trans.shared.b16 {%0,%1,%2,%3}, [%4];"
                 : "=r"(r0), "=r"(r1), "=r"(r2), "=r"(r3) : "r"(addr));
}
__device__ __forceinline__ void mma_bf16(float* d, const uint32_t* a,
                                         const uint32_t* b) {
    asm volatile(
        "mma.sync.aligned.m16n8k16.row.col.f32.bf16.bf16.f32 "
        "{%0,%1,%2,%3}, {%4,%5,%6,%7}, {%8,%9}, {%0,%1,%2,%3};"
        : "+f"(d[0]), "+f"(d[1]), "+f"(d[2]), "+f"(d[3])
        : "r"(a[0]), "r"(a[1]), "r"(a[2]), "r"(a[3]), "r"(b[0]), "r"(b[1]));
}
__device__ __forceinline__ void cp_async16(uint32_t dst, const void* src) {
    asm volatile("cp.async.cg.shared.global [%0], [%1], 16;" :: "r"(dst), "l"(src));
}
__device__ __forceinline__ void cp_commit() {
    asm volatile("cp.async.commit_group;" ::: "memory");
}
template<int N> __device__ __forceinline__ void cp_wait() {
    asm volatile("cp.async.wait_group %0;" :: "n"(N) : "memory");
}

// split (x,y) -> packed bf16x2 hi and lo words
__device__ __forceinline__ void split2(float x, float y,
                                       uint32_t& hi, uint32_t& lo) {
    __nv_bfloat16 hx = __float2bfloat16(x);
    __nv_bfloat16 hy = __float2bfloat16(y);
    __nv_bfloat16 lx = __float2bfloat16(x - __bfloat162float(hx));
    __nv_bfloat16 ly = __float2bfloat16(y - __bfloat162float(hy));
    __nv_bfloat162 hp = __halves2bfloat162(hx, hy);
    __nv_bfloat162 lp = __halves2bfloat162(lx, ly);
    hi = *(uint32_t*)&hp;
    lo = *(uint32_t*)&lp;
}

// ===========================================================================
// Mask normalization (dtype-agnostic)
// ===========================================================================
__global__ void mask_detect_kernel(const unsigned char* __restrict__ m)
{
    __shared__ int s_nz, s_f32;
    if (threadIdx.x == 0) { s_nz = 0; s_f32 = 0; }
    __syncthreads();
    int nz = 0, f32 = 0;
    for (int i = threadIdx.x; i < MROWS; i += 256) {
        unsigned char v = m[i];
        if ((i & 3) != 0 && v != 0) nz = 1;
        if ((i & 3) == 3 && v == 0x3F) f32 = 1;
    }
    if (nz)  atomicOr(&s_nz, 1);
    if (f32) atomicOr(&s_f32, 1);
    __syncthreads();
    if (threadIdx.x == 0)
        g_mask_mode = s_f32 ? 2 : (s_nz ? 0 : 1);
}

__global__ void mask_expand_kernel(const void* __restrict__ m)
{
    int i = blockIdx.x * 256 + threadIdx.x;
    if (i >= MROWS) return;
    int mode = g_mask_mode;
    unsigned char r;
    if (mode == 0)      r = ((const unsigned char*)m)[i] != 0;
    else if (mode == 1) r = ((const int*)m)[i] != 0;
    else                r = ((const float*)m)[i] != 0.0f;
    g_mask[i] = r;
}

// ===========================================================================
// Pre-split fp32 -> bf16 hi/lo (vectorized, n4 = count/4)
// ===========================================================================
__global__ void presplit_kernel(const float* __restrict__ src,
                                __nv_bfloat16* __restrict__ hi,
                                __nv_bfloat16* __restrict__ lo, int n4)
{
    int i = blockIdx.x * 256 + threadIdx.x;
    if (i >= n4) return;
    float4 v = ((const float4*)src)[i];
    uint32_t h0, l0, h1, l1;
    split2(v.x, v.y, h0, l0);
    split2(v.z, v.w, h1, l1);
    uint2 hh, ll;
    hh.x = h0; hh.y = h1;
    ll.x = l0; ll.y = l1;
    ((uint2*)hi)[i] = hh;
    ((uint2*)lo)[i] = ll;
}

// ===========================================================================
// 2-stage pipelined split-bf16 HMMA GEMM.
// C = A(hi+lo)[M,1024] * B(hi+lo)[N,1024]^T + bias.
// CTA 128x64, K-chunk 64, 8 warps (4m x 2n), warp tile 32x32.
// smem rows: 64 bf16 padded to 72 (144B). Stage = AH|AL|BH|BL.
// ===========================================================================
#define GST   55296
#define G_AH  0
#define G_AL  18432
#define G_BH  36864
#define G_BL  46080
#define G_TOTAL (2 * GST)     // 110592

template<bool SPLIT_OUT>
__global__ __launch_bounds__(256, 2)
void gemm_mma2(const __nv_bfloat16* __restrict__ Ah,
               const __nv_bfloat16* __restrict__ Al,
               const __nv_bfloat16* __restrict__ Bh,
               const __nv_bfloat16* __restrict__ Bl,
               const float* __restrict__ bias,
               float* __restrict__ C,
               __nv_bfloat16* __restrict__ Ch,
               __nv_bfloat16* __restrict__ Cl,
               int N)
{
    extern __shared__ char sm[];
    uint32_t sbase = smem_u32(sm);
    int tid  = threadIdx.x;
    int lane = tid & 31;
    int wid  = tid >> 5;
    int warp_m = wid & 3;
    int warp_n = wid >> 2;
    int m0 = blockIdx.y * 128;
    int n0 = blockIdx.x * 64;

    float acc[2][4][4];
#pragma unroll
    for (int i = 0; i < 2; i++)
#pragma unroll
        for (int j = 0; j < 4; j++)
#pragma unroll
            for (int c = 0; c < 4; c++) acc[i][j][c] = 0.f;

    // ---- tile issue (12 cp.async / thread) ----
    auto issue = [&](int k0, uint32_t st) {
#pragma unroll
        for (int it = 0; it < 4; it++) {
            int idx = tid + it * 256;        // 0..1023
            int row = idx >> 3, cg = idx & 7;
            size_t g = (size_t)(m0 + row) * K_DIM + k0 + cg * 8;
            uint32_t d = sbase + st + (uint32_t)(row * 144 + cg * 16);
            cp_async16(d + G_AH, Ah + g);
            cp_async16(d + G_AL, Al + g);
        }
#pragma unroll
        for (int it = 0; it < 2; it++) {
            int idx = tid + it * 256;        // 0..511
            int row = idx >> 3, cg = idx & 7;
            size_t g = (size_t)(n0 + row) * K_DIM + k0 + cg * 8;
            uint32_t d = sbase + st + (uint32_t)(row * 144 + cg * 16);
            cp_async16(d + G_BH, Bh + g);
            cp_async16(d + G_BL, Bl + g);
        }
    };

    issue(0, 0);
    cp_commit();

    for (int c = 0; c < 16; c++) {
        uint32_t st = (c & 1) ? GST : 0;
        if (c + 1 < 16) {
            issue((c + 1) * 64, ((c + 1) & 1) ? GST : 0);
            cp_commit();
            cp_wait<1>();
        } else {
            cp_wait<0>();
        }
        __syncthreads();

#pragma unroll
        for (int ks = 0; ks < 4; ks++) {
            uint32_t ahi[2][4], alo[2][4];
#pragma unroll
            for (int mf = 0; mf < 2; mf++) {
                int row = warp_m * 32 + mf * 16 + (lane & 15);
                int col = ks * 16 + (lane >> 4) * 8;
                uint32_t ad = sbase + st + (uint32_t)(row * 144 + col * 2);
                ldmatrix_x4(ahi[mf][0], ahi[mf][1], ahi[mf][2], ahi[mf][3], ad + G_AH);
                ldmatrix_x4(alo[mf][0], alo[mf][1], alo[mf][2], alo[mf][3], ad + G_AL);
            }
            uint32_t bhi[4][2], blo[4][2];
#pragma unroll
            for (int np = 0; np < 2; np++) {
                int row = warp_n * 32 + (np * 2 + (lane >> 4)) * 8 + (lane & 7);
                int col = ks * 16 + ((lane >> 3) & 1) * 8;
                uint32_t ad = sbase + st + (uint32_t)(row * 144 + col * 2);
                uint32_t r0, r1, r2, r3;
                ldmatrix_x4(r0, r1, r2, r3, ad + G_BH);
                bhi[np * 2][0] = r0; bhi[np * 2][1] = r1;
                bhi[np * 2 + 1][0] = r2; bhi[np * 2 + 1][1] = r3;
                ldmatrix_x4(r0, r1, r2, r3, ad + G_BL);
                blo[np * 2][0] = r0; blo[np * 2][1] = r1;
                blo[np * 2 + 1][0] = r2; blo[np * 2 + 1][1] = r3;
            }
#pragma unroll
            for (int mf = 0; mf < 2; mf++)
#pragma unroll
                for (int nf = 0; nf < 4; nf++) {
                    mma_bf16(acc[mf][nf], ahi[mf], bhi[nf]);
                    mma_bf16(acc[mf][nf], ahi[mf], blo[nf]);
                    mma_bf16(acc[mf][nf], alo[mf], bhi[nf]);
                }
        }
        __syncthreads();
    }

    // ---- epilogue ----
#pragma unroll
    for (int mf = 0; mf < 2; mf++) {
#pragma unroll
        for (int nf = 0; nf < 4; nf++) {
            int row = m0 + warp_m * 32 + mf * 16 + (lane >> 2);
            int col = n0 + warp_n * 32 + nf * 8 + (lane & 3) * 2;
            float b0 = bias[col], b1 = bias[col + 1];
            float d0 = acc[mf][nf][0] + b0;
            float d1 = acc[mf][nf][1] + b1;
            float d2 = acc[mf][nf][2] + b0;
            float d3 = acc[mf][nf][3] + b1;
            if (SPLIT_OUT) {
                uint32_t hw, lw;
                split2(d0, d1, hw, lw);
                *(uint32_t*)(Ch + (size_t)row * N + col) = hw;
                *(uint32_t*)(Cl + (size_t)row * N + col) = lw;
                split2(d2, d3, hw, lw);
                *(uint32_t*)(Ch + (size_t)(row + 8) * N + col) = hw;
                *(uint32_t*)(Cl + (size_t)(row + 8) * N + col) = lw;
            } else {
                C[(size_t)row * N + col]           = d0;
                C[(size_t)row * N + col + 1]       = d1;
                C[(size_t)(row + 8) * N + col]     = d2;
                C[(size_t)(row + 8) * N + col + 1] = d3;
            }
        }
    }
}

// ===========================================================================
// Flash attention, split-bf16 mma.sync, 2-stage cp.async K/V pipeline.
// Grid: (T/128, H, B), 8 warps x 16 q-rows. Inputs pre-split qkv hi/lo.
// Scaling 0.125 applied to S after MMA (exact).
// ===========================================================================
#define F_QH   0
#define F_QL   18432
#define F_ST0  36864
#define F_ST1  73728
#define F_KH   0
#define F_KL   9216
#define F_VH   18432
#define F_VL   27648
#define F_MSK0 110592
#define F_MSK1 110848
#define F_TOTAL 111104

__global__ __launch_bounds__(256, 2)
void flash_mma2(const __nv_bfloat16* __restrict__ qh,
                const __nv_bfloat16* __restrict__ ql,
                __nv_bfloat16* __restrict__ attn_hi,
                __nv_bfloat16* __restrict__ attn_lo)
{
    extern __shared__ char sm[];
    uint32_t sbase = smem_u32(sm);
    float* msk0 = (float*)(sm + F_MSK0);
    float* msk1 = (float*)(sm + F_MSK1);
    int tid = threadIdx.x;
    int lane = tid & 31;
    int w = tid >> 5;
    int b = blockIdx.z;
    int h = blockIdx.y;
    int q0 = blockIdx.x * 128;
    int qrow0 = w * 16;

    // ---- stage Q tile (group 0) ----
#pragma unroll
    for (int it = 0; it < 4; it++) {
        int idx = tid + it * 256;
        int row = idx >> 3, cg = idx & 7;
        size_t g = (size_t)((q0 + row) * 2 + b) * 3072 + h * 64 + cg * 8;
        uint32_t d = sbase + (uint32_t)(row * 144 + cg * 16);
        cp_async16(d + F_QH, qh + g);
        cp_async16(d + F_QL, ql + g);
    }
    cp_commit();

    auto issue_kv = [&](int s0, uint32_t st) {
#pragma unroll
        for (int it = 0; it < 2; it++) {
            int idx = tid + it * 256;
            int row = idx >> 3, cg = idx & 7;
            size_t g = (size_t)((s0 + row) * 2 + b) * 3072 + h * 64 + cg * 8;
            uint32_t d = sbase + st + (uint32_t)(row * 144 + cg * 16);
            cp_async16(d + F_KH, qh + g + E_DIM);
            cp_async16(d + F_KL, ql + g + E_DIM);
            cp_async16(d + F_VH, qh + g + 2 * E_DIM);
            cp_async16(d + F_VL, ql + g + 2 * E_DIM);
        }
    };

    // ---- stage tile 0 (group 1) ----
    issue_kv(0, F_ST0);
    if (tid < 64)
        msk0[tid] = g_mask[tid * B_DIM + b] ? NEG_INF_F : 0.f;
    cp_commit();

    float m1 = -3.0e38f, m2 = -3.0e38f, l1 = 0.f, l2 = 0.f;
    float o[8][4];
#pragma unroll
    for (int nf = 0; nf < 8; nf++)
#pragma unroll
        for (int c = 0; c < 4; c++) o[nf][c] = 0.f;

    for (int c = 0; c < 32; c++) {
        uint32_t st = (c & 1) ? F_ST1 : F_ST0;
        float* mk = (c & 1) ? msk1 : msk0;
        if (c + 1 < 32) {
            issue_kv((c + 1) * 64, ((c + 1) & 1) ? F_ST1 : F_ST0);
            float* mkn = ((c + 1) & 1) ? msk1 : msk0;
            if (tid < 64)
                mkn[tid] = g_mask[((c + 1) * 64 + tid) * B_DIM + b] ? NEG_INF_F : 0.f;
            cp_commit();
            cp_wait<1>();
        } else {
            cp_wait<0>();
        }
        __syncthreads();

        // ---- S = Q K^T (3-pass split) ----
        float acc[8][4];
#pragma unroll
        for (int nf = 0; nf < 8; nf++)
#pragma unroll
            for (int cc = 0; cc < 4; cc++) acc[nf][cc] = 0.f;

#pragma unroll
        for (int kf = 0; kf < 4; kf++) {
            uint32_t qhi[4], qlo[4];
            {
                int row = qrow0 + (lane & 15);
                int col = kf * 16 + (lane >> 4) * 8;
                uint32_t ad = sbase + (uint32_t)(row * 144 + col * 2);
                ldmatrix_x4(qhi[0], qhi[1], qhi[2], qhi[3], ad + F_QH);
                ldmatrix_x4(qlo[0], qlo[1], qlo[2], qlo[3], ad + F_QL);
            }
#pragma unroll
            for (int np = 0; np < 4; np++) {
                int row = (np * 2 + (lane >> 4)) * 8 + (lane & 7);
                int col = kf * 16 + ((lane >> 3) & 1) * 8;
                uint32_t ad = sbase + st + (uint32_t)(row * 144 + col * 2);
                uint32_t khi[4], klo[4];
                ldmatrix_x4(khi[0], khi[1], khi[2], khi[3], ad + F_KH);
                ldmatrix_x4(klo[0], klo[1], klo[2], klo[3], ad + F_KL);
                mma_bf16(acc[np * 2],     qhi, khi);
                mma_bf16(acc[np * 2],     qhi, klo);
                mma_bf16(acc[np * 2],     qlo, khi);
                mma_bf16(acc[np * 2 + 1], qhi, khi + 2);
                mma_bf16(acc[np * 2 + 1], qhi, klo + 2);
                mma_bf16(acc[np * 2 + 1], qlo, khi + 2);
            }
        }

        // ---- scale + mask ----
#pragma unroll
        for (int nf = 0; nf < 8; nf++) {
            float2 mv = *(float2*)&mk[nf * 8 + (lane & 3) * 2];
            acc[nf][0] = acc[nf][0] * 0.125f + mv.x;
            acc[nf][1] = acc[nf][1] * 0.125f + mv.y;
            acc[nf][2] = acc[nf][2] * 0.125f + mv.x;
            acc[nf][3] = acc[nf][3] * 0.125f + mv.y;
        }

        // ---- online softmax ----
        float mx1 = -3.0e38f, mx2 = -3.0e38f;
#pragma unroll
        for (int nf = 0; nf < 8; nf++) {
            mx1 = fmaxf(mx1, fmaxf(acc[nf][0], acc[nf][1]));
            mx2 = fmaxf(mx2, fmaxf(acc[nf][2], acc[nf][3]));
        }
        mx1 = fmaxf(mx1, __shfl_xor_sync(0xffffffffu, mx1, 1));
        mx1 = fmaxf(mx1, __shfl_xor_sync(0xffffffffu, mx1, 2));
        mx2 = fmaxf(mx2, __shfl_xor_sync(0xffffffffu, mx2, 1));
        mx2 = fmaxf(mx2, __shfl_xor_sync(0xffffffffu, mx2, 2));

        float mn1 = fmaxf(m1, mx1);
        float mn2 = fmaxf(m2, mx2);
        float al1 = __expf(m1 - mn1);
        float al2 = __expf(m2 - mn2);
        float rs1 = 0.f, rs2 = 0.f;
#pragma unroll
        for (int nf = 0; nf < 8; nf++) {
            acc[nf][0] = __expf(acc[nf][0] - mn1);
            acc[nf][1] = __expf(acc[nf][1] - mn1);
            acc[nf][2] = __expf(acc[nf][2] - mn2);
            acc[nf][3] = __expf(acc[nf][3] - mn2);
            rs1 += acc[nf][0] + acc[nf][1];
            rs2 += acc[nf][2] + acc[nf][3];
        }
        rs1 += __shfl_xor_sync(0xffffffffu, rs1, 1);
        rs1 += __shfl_xor_sync(0xffffffffu, rs1, 2);
        rs2 += __shfl_xor_sync(0xffffffffu, rs2, 1);
        rs2 += __shfl_xor_sync(0xffffffffu, rs2, 2);
        l1 = l1 * al1 + rs1;
        l2 = l2 * al2 + rs2;
        m1 = mn1; m2 = mn2;

#pragma unroll
        for (int nf = 0; nf < 8; nf++) {
            o[nf][0] *= al1; o[nf][1] *= al1;
            o[nf][2] *= al2; o[nf][3] *= al2;
        }

        // ---- O += P V (3-pass split, P frags in registers) ----
#pragma unroll
        for (int kf = 0; kf < 4; kf++) {
            uint32_t phi[4], plo[4];
            split2(acc[2 * kf][0],     acc[2 * kf][1],     phi[0], plo[0]);
            split2(acc[2 * kf][2],     acc[2 * kf][3],     phi[1], plo[1]);
            split2(acc[2 * kf + 1][0], acc[2 * kf + 1][1], phi[2], plo[2]);
            split2(acc[2 * kf + 1][2], acc[2 * kf + 1][3], phi[3], plo[3]);
#pragma unroll
            for (int np = 0; np < 4; np++) {
                int row = kf * 16 + (lane & 15);
                int col = (np * 2 + (lane >> 4)) * 8;
                uint32_t ad = sbase + st + (uint32_t)(row * 144 + col * 2);
                uint32_t vhi[4], vlo[4];
                ldmatrix_x4_trans(vhi[0], vhi[1], vhi[2], vhi[3], ad + F_VH);
                ldmatrix_x4_trans(vlo[0], vlo[1], vlo[2], vlo[3], ad + F_VL);
                mma_bf16(o[np * 2],     phi, vhi);
                mma_bf16(o[np * 2],     phi, vlo);
                mma_bf16(o[np * 2],     plo, vhi);
                mma_bf16(o[np * 2 + 1], phi, vhi + 2);
                mma_bf16(o[np * 2 + 1], phi, vlo + 2);
                mma_bf16(o[np * 2 + 1], plo, vhi + 2);
            }
        }
        __syncthreads();
    }

    // ---- epilogue: normalize, split, write bf16 hi/lo ----
    float inv1 = 1.f / l1;
    float inv2 = 1.f / l2;
    int t1 = q0 + qrow0 + (lane >> 2);
    int t2 = t1 + 8;
#pragma unroll
    for (int nf = 0; nf < 8; nf++) {
        int d = h * 64 + nf * 8 + (lane & 3) * 2;
        size_t r1 = (size_t)(t1 * 2 + b) * E_DIM + d;
        size_t r2 = (size_t)(t2 * 2 + b) * E_DIM + d;
        uint32_t hw, lw;
        split2(o[nf][0] * inv1, o[nf][1] * inv1, hw, lw);
        *(uint32_t*)(attn_hi + r1) = hw;
        *(uint32_t*)(attn_lo + r1) = lw;
        split2(o[nf][2] * inv2, o[nf][3] * inv2, hw, lw);
        *(uint32_t*)(attn_hi + r2) = hw;
        *(uint32_t*)(attn_lo + r2) = lw;
    }
}

// ===========================================================================
extern "C" void kernel_launch(void* const* d_in, const int* in_sizes, int n_in,
                              void* d_out, int out_size)
{
    const float* x      = (const float*)d_in[0];
    const float* w_in   = (const float*)d_in[1];
    const float* b_in   = (const float*)d_in[2];
    const float* w_out  = (const float*)d_in[3];
    const float* b_out  = (const float*)d_in[4];
    const void*  mask   = d_in[5];
    float* out = (float*)d_out;

    __nv_bfloat16 *x_hi, *x_lo, *win_hi, *win_lo, *wout_hi, *wout_lo;
    __nv_bfloat16 *qkv_hi, *qkv_lo, *attn_hi, *attn_lo;
    cudaGetSymbolAddress((void**)&x_hi, g_x_hi);
    cudaGetSymbolAddress((void**)&x_lo, g_x_lo);
    cudaGetSymbolAddress((void**)&win_hi, g_win_hi);
    cudaGetSymbolAddress((void**)&win_lo, g_win_lo);
    cudaGetSymbolAddress((void**)&wout_hi, g_wout_hi);
    cudaGetSymbolAddress((void**)&wout_lo, g_wout_lo);
    cudaGetSymbolAddress((void**)&qkv_hi, g_qkv_hi);
    cudaGetSymbolAddress((void**)&qkv_lo, g_qkv_lo);
    cudaGetSymbolAddress((void**)&attn_hi, g_attn_hi);
    cudaGetSymbolAddress((void**)&attn_lo, g_attn_lo);

    cudaFuncSetAttribute(gemm_mma2<true>,
                         cudaFuncAttributeMaxDynamicSharedMemorySize, G_TOTAL);
    cudaFuncSetAttribute(gemm_mma2<false>,
                         cudaFuncAttributeMaxDynamicSharedMemorySize, G_TOTAL);
    cudaFuncSetAttribute(flash_mma2,
                         cudaFuncAttributeMaxDynamicSharedMemorySize, F_TOTAL);

    // 0) normalize mask + pre-split inputs
    mask_detect_kernel<<<1, 256>>>((const unsigned char*)mask);
    mask_expand_kernel<<<(MROWS + 255) / 256, 256>>>(mask);
    presplit_kernel<<<(MROWS * E_DIM / 4 + 255) / 256, 256>>>(x, x_hi, x_lo,
                                                              MROWS * E_DIM / 4);
    presplit_kernel<<<(3 * E_DIM * E_DIM / 4 + 255) / 256, 256>>>(
        w_in, win_hi, win_lo, 3 * E_DIM * E_DIM / 4);
    presplit_kernel<<<(E_DIM * E_DIM / 4 + 255) / 256, 256>>>(
        w_out, wout_hi, wout_lo, E_DIM * E_DIM / 4);

    // 1) qkv = x @ W_in^T + b_in  -> split bf16  [4096 x 3072]
    {
        dim3 grid((3 * E_DIM) / 64, MROWS / 128);
        gemm_mma2<true><<<grid, 256, G_TOTAL>>>(x_hi, x_lo, win_hi, win_lo,
                                                b_in, nullptr,
                                                qkv_hi, qkv_lo, 3 * E_DIM);
    }

    // 2) flash attention -> split bf16 attn
    {
        dim3 grid(T_DIM / 128, H_DIM, B_DIM);
        flash_mma2<<<grid, 256, F_TOTAL>>>(qkv_hi, qkv_lo, attn_hi, attn_lo);
    }

    // 3) out = attn @ W_out^T + b_out   [4096 x 1024] fp32
    {
        dim3 grid(E_DIM / 64, MROWS / 128);
        gemm_mma2<false><<<grid, 256, G_TOTAL>>>(attn_hi, attn_lo,
                                                 wout_hi, wout_lo,
                                                 b_out, out,
                                                 nullptr, nullptr, E_DIM);
    }
}

// round 7
// speedup vs baseline: 3.8702x; 1.0425x over previous
#include <cuda_runtime.h>
#include <cuda_bf16.h>
#include <cstdint>
#include <cstddef>

#define T_DIM 2048
#define B_DIM 2
#define E_DIM 1024
#define H_DIM 16
#define MROWS (T_DIM * B_DIM)      // 4096
#define K_DIM 1024
#define NEG_INF_F (-1e24f)

// ---------------------------------------------------------------------------
// Scratch (no cudaMalloc allowed) — all bf16 hi/lo split pairs
// ---------------------------------------------------------------------------
__device__ __nv_bfloat16 g_x_hi[(size_t)MROWS * E_DIM];
__device__ __nv_bfloat16 g_x_lo[(size_t)MROWS * E_DIM];
__device__ __nv_bfloat16 g_win_hi[(size_t)3 * E_DIM * E_DIM];
__device__ __nv_bfloat16 g_win_lo[(size_t)3 * E_DIM * E_DIM];
__device__ __nv_bfloat16 g_wout_hi[(size_t)E_DIM * E_DIM];
__device__ __nv_bfloat16 g_wout_lo[(size_t)E_DIM * E_DIM];
__device__ __nv_bfloat16 g_qkv_hi[(size_t)MROWS * 3 * E_DIM];
__device__ __nv_bfloat16 g_qkv_lo[(size_t)MROWS * 3 * E_DIM];
__device__ __nv_bfloat16 g_attn_hi[(size_t)MROWS * E_DIM];
__device__ __nv_bfloat16 g_attn_lo[(size_t)MROWS * E_DIM];
__device__ int g_mask_mode;
__device__ unsigned char g_mask[MROWS];

// ===========================================================================
// PTX helpers (base sm_103 only: mma.sync / ldmatrix / cp.async)
// ===========================================================================
__device__ __forceinline__ uint32_t smem_u32(const void* p) {
    uint32_t a;
    asm("{ .reg .u64 t; cvta.to.shared.u64 t, %1; cvt.u32.u64 %0, t; }"
        : "=r"(a) : "l"(p));
    return a;
}
__device__ __forceinline__ void ldmatrix_x4(uint32_t& r0, uint32_t& r1,
                                            uint32_t& r2, uint32_t& r3,
                                            uint32_t addr) {
    asm volatile("ldmatrix.sync.aligned.m8n8.x4.shared.b16 {%0,%1,%2,%3}, [%4];"
                 : "=r"(r0), "=r"(r1), "=r"(r2), "=r"(r3) : "r"(addr));
}
__device__ __forceinline__ void ldmatrix_x4_trans(uint32_t& r0, uint32_t& r1,
                                                  uint32_t& r2, uint32_t& r3,
                                                  uint32_t addr) {
    asm volatile("ldmatrix.sync.aligned.m8n8.x4.trans.shared.b16 {%0,%1,%2,%3}, [%4];"
                 : "=r"(r0), "=r"(r1), "=r"(r2), "=r"(r3) : "r"(addr));
}
__device__ __forceinline__ void mma_bf16(float* d, const uint32_t* a,
                                         const uint32_t* b) {
    asm volatile(
        "mma.sync.aligned.m16n8k16.row.col.f32.bf16.bf16.f32 "
        "{%0,%1,%2,%3}, {%4,%5,%6,%7}, {%8,%9}, {%0,%1,%2,%3};"
        : "+f"(d[0]), "+f"(d[1]), "+f"(d[2]), "+f"(d[3])
        : "r"(a[0]), "r"(a[1]), "r"(a[2]), "r"(a[3]), "r"(b[0]), "r"(b[1]));
}
__device__ __forceinline__ void cp_async16(uint32_t dst, const void* src) {
    asm volatile("cp.async.cg.shared.global [%0], [%1], 16;" :: "r"(dst), "l"(src));
}
__device__ __forceinline__ void cp_commit() {
    asm volatile("cp.async.commit_group;" ::: "memory");
}
template<int N> __device__ __forceinline__ void cp_wait() {
    asm volatile("cp.async.wait_group %0;" :: "n"(N) : "memory");
}

// split (x,y) -> packed bf16x2 hi and lo words
__device__ __forceinline__ void split2(float x, float y,
                                       uint32_t& hi, uint32_t& lo) {
    __nv_bfloat16 hx = __float2bfloat16(x);
    __nv_bfloat16 hy = __float2bfloat16(y);
    __nv_bfloat16 lx = __float2bfloat16(x - __bfloat162float(hx));
    __nv_bfloat16 ly = __float2bfloat16(y - __bfloat162float(hy));
    __nv_bfloat162 hp = __halves2bfloat162(hx, hy);
    __nv_bfloat162 lp = __halves2bfloat162(lx, ly);
    hi = *(uint32_t*)&hp;
    lo = *(uint32_t*)&lp;
}

// ===========================================================================
// Mask normalization (dtype-agnostic)
// ===========================================================================
__global__ void mask_detect_kernel(const unsigned char* __restrict__ m)
{
    __shared__ int s_nz, s_f32;
    if (threadIdx.x == 0) { s_nz = 0; s_f32 = 0; }
    __syncthreads();
    int nz = 0, f32 = 0;
    for (int i = threadIdx.x; i < MROWS; i += 256) {
        unsigned char v = m[i];
        if ((i & 3) != 0 && v != 0) nz = 1;
        if ((i & 3) == 3 && v == 0x3F) f32 = 1;
    }
    if (nz)  atomicOr(&s_nz, 1);
    if (f32) atomicOr(&s_f32, 1);
    __syncthreads();
    if (threadIdx.x == 0)
        g_mask_mode = s_f32 ? 2 : (s_nz ? 0 : 1);
}

__global__ void mask_expand_kernel(const void* __restrict__ m)
{
    int i = blockIdx.x * 256 + threadIdx.x;
    if (i >= MROWS) return;
    int mode = g_mask_mode;
    unsigned char r;
    if (mode == 0)      r = ((const unsigned char*)m)[i] != 0;
    else if (mode == 1) r = ((const int*)m)[i] != 0;
    else                r = ((const float*)m)[i] != 0.0f;
    g_mask[i] = r;
}

// ===========================================================================
// Pre-split fp32 -> bf16 hi/lo
// ===========================================================================
__global__ void presplit_kernel(const float* __restrict__ src,
                                __nv_bfloat16* __restrict__ hi,
                                __nv_bfloat16* __restrict__ lo, int n4)
{
    int i = blockIdx.x * 256 + threadIdx.x;
    if (i >= n4) return;
    float4 v = ((const float4*)src)[i];
    uint32_t h0, l0, h1, l1;
    split2(v.x, v.y, h0, l0);
    split2(v.z, v.w, h1, l1);
    uint2 hh, ll;
    hh.x = h0; hh.y = h1;
    ll.x = l0; ll.y = l1;
    ((uint2*)hi)[i] = hh;
    ((uint2*)lo)[i] = ll;
}

// ===========================================================================
// 2-stage pipelined split-bf16 HMMA GEMM (unchanged core).
// scale_n: columns [0, scale_n) are multiplied by 0.125 AFTER bias
// (folds attention scaling into the q section of qkv).
// ===========================================================================
#define GST   55296
#define G_AH  0
#define G_AL  18432
#define G_BH  36864
#define G_BL  46080
#define G_TOTAL (2 * GST)     // 110592

template<bool SPLIT_OUT>
__global__ __launch_bounds__(256, 2)
void gemm_mma2(const __nv_bfloat16* __restrict__ Ah,
               const __nv_bfloat16* __restrict__ Al,
               const __nv_bfloat16* __restrict__ Bh,
               const __nv_bfloat16* __restrict__ Bl,
               const float* __restrict__ bias,
               float* __restrict__ C,
               __nv_bfloat16* __restrict__ Ch,
               __nv_bfloat16* __restrict__ Cl,
               int N, int scale_n)
{
    extern __shared__ char sm[];
    uint32_t sbase = smem_u32(sm);
    int tid  = threadIdx.x;
    int lane = tid & 31;
    int wid  = tid >> 5;
    int warp_m = wid & 3;
    int warp_n = wid >> 2;
    int m0 = blockIdx.y * 128;
    int n0 = blockIdx.x * 64;

    float acc[2][4][4];
#pragma unroll
    for (int i = 0; i < 2; i++)
#pragma unroll
        for (int j = 0; j < 4; j++)
#pragma unroll
            for (int c = 0; c < 4; c++) acc[i][j][c] = 0.f;

    auto issue = [&](int k0, uint32_t st) {
#pragma unroll
        for (int it = 0; it < 4; it++) {
            int idx = tid + it * 256;
            int row = idx >> 3, cg = idx & 7;
            size_t g = (size_t)(m0 + row) * K_DIM + k0 + cg * 8;
            uint32_t d = sbase + st + (uint32_t)(row * 144 + cg * 16);
            cp_async16(d + G_AH, Ah + g);
            cp_async16(d + G_AL, Al + g);
        }
#pragma unroll
        for (int it = 0; it < 2; it++) {
            int idx = tid + it * 256;
            int row = idx >> 3, cg = idx & 7;
            size_t g = (size_t)(n0 + row) * K_DIM + k0 + cg * 8;
            uint32_t d = sbase + st + (uint32_t)(row * 144 + cg * 16);
            cp_async16(d + G_BH, Bh + g);
            cp_async16(d + G_BL, Bl + g);
        }
    };

    issue(0, 0);
    cp_commit();

    for (int c = 0; c < 16; c++) {
        uint32_t st = (c & 1) ? GST : 0;
        if (c + 1 < 16) {
            issue((c + 1) * 64, ((c + 1) & 1) ? GST : 0);
            cp_commit();
            cp_wait<1>();
        } else {
            cp_wait<0>();
        }
        __syncthreads();

#pragma unroll
        for (int ks = 0; ks < 4; ks++) {
            uint32_t ahi[2][4], alo[2][4];
#pragma unroll
            for (int mf = 0; mf < 2; mf++) {
                int row = warp_m * 32 + mf * 16 + (lane & 15);
                int col = ks * 16 + (lane >> 4) * 8;
                uint32_t ad = sbase + st + (uint32_t)(row * 144 + col * 2);
                ldmatrix_x4(ahi[mf][0], ahi[mf][1], ahi[mf][2], ahi[mf][3], ad + G_AH);
                ldmatrix_x4(alo[mf][0], alo[mf][1], alo[mf][2], alo[mf][3], ad + G_AL);
            }
            uint32_t bhi[4][2], blo[4][2];
#pragma unroll
            for (int np = 0; np < 2; np++) {
                int row = warp_n * 32 + (np * 2 + (lane >> 4)) * 8 + (lane & 7);
                int col = ks * 16 + ((lane >> 3) & 1) * 8;
                uint32_t ad = sbase + st + (uint32_t)(row * 144 + col * 2);
                uint32_t r0, r1, r2, r3;
                ldmatrix_x4(r0, r1, r2, r3, ad + G_BH);
                bhi[np * 2][0] = r0; bhi[np * 2][1] = r1;
                bhi[np * 2 + 1][0] = r2; bhi[np * 2 + 1][1] = r3;
                ldmatrix_x4(r0, r1, r2, r3, ad + G_BL);
                blo[np * 2][0] = r0; blo[np * 2][1] = r1;
                blo[np * 2 + 1][0] = r2; blo[np * 2 + 1][1] = r3;
            }
#pragma unroll
            for (int mf = 0; mf < 2; mf++)
#pragma unroll
                for (int nf = 0; nf < 4; nf++) {
                    mma_bf16(acc[mf][nf], ahi[mf], bhi[nf]);
                    mma_bf16(acc[mf][nf], ahi[mf], blo[nf]);
                    mma_bf16(acc[mf][nf], alo[mf], bhi[nf]);
                }
        }
        __syncthreads();
    }

#pragma unroll
    for (int mf = 0; mf < 2; mf++) {
#pragma unroll
        for (int nf = 0; nf < 4; nf++) {
            int row = m0 + warp_m * 32 + mf * 16 + (lane >> 2);
            int col = n0 + warp_n * 32 + nf * 8 + (lane & 3) * 2;
            float sc = (col < scale_n) ? 0.125f : 1.0f;
            float b0 = bias[col], b1 = bias[col + 1];
            float d0 = (acc[mf][nf][0] + b0) * sc;
            float d1 = (acc[mf][nf][1] + b1) * sc;
            float d2 = (acc[mf][nf][2] + b0) * sc;
            float d3 = (acc[mf][nf][3] + b1) * sc;
            if (SPLIT_OUT) {
                uint32_t hw, lw;
                split2(d0, d1, hw, lw);
                *(uint32_t*)(Ch + (size_t)row * N + col) = hw;
                *(uint32_t*)(Cl + (size_t)row * N + col) = lw;
                split2(d2, d3, hw, lw);
                *(uint32_t*)(Ch + (size_t)(row + 8) * N + col) = hw;
                *(uint32_t*)(Cl + (size_t)(row + 8) * N + col) = lw;
            } else {
                C[(size_t)row * N + col]           = d0;
                C[(size_t)row * N + col + 1]       = d1;
                C[(size_t)(row + 8) * N + col]     = d2;
                C[(size_t)(row + 8) * N + col + 1] = d3;
            }
        }
    }
}

// ===========================================================================
// Flash attention v3: 128 threads = 4 warps x 32 q-rows (mf=2).
// Halves LDSM redundancy on K/V. Fixed-reference softmax (m=0; safe since
// |scores| << fp32 exp range; q pre-scaled by 0.125 in GEMM1 epilogue).
// ===========================================================================
#define F_QH   0
#define F_QL   18432
#define F_ST0  36864
#define F_ST1  73728
#define F_KH   0
#define F_KL   9216
#define F_VH   18432
#define F_VL   27648
#define F_MSK0 110592
#define F_MSK1 110848
#define F_TOTAL 111104

__global__ __launch_bounds__(128, 2)
void flash_mma3(const __nv_bfloat16* __restrict__ qh,
                const __nv_bfloat16* __restrict__ ql,
                __nv_bfloat16* __restrict__ attn_hi,
                __nv_bfloat16* __restrict__ attn_lo)
{
    extern __shared__ char sm[];
    uint32_t sbase = smem_u32(sm);
    float* msk0 = (float*)(sm + F_MSK0);
    float* msk1 = (float*)(sm + F_MSK1);
    int tid = threadIdx.x;
    int lane = tid & 31;
    int w = tid >> 5;                 // 0..3
    int b = blockIdx.z;
    int h = blockIdx.y;
    int q0 = blockIdx.x * 128;
    int qbase = w * 32;

    // ---- stage Q tile 128x64 hi/lo ----
#pragma unroll
    for (int it = 0; it < 8; it++) {
        int idx = tid + it * 128;     // 0..1023
        int row = idx >> 3, cg = idx & 7;
        size_t g = (size_t)((q0 + row) * 2 + b) * 3072 + h * 64 + cg * 8;
        uint32_t d = sbase + (uint32_t)(row * 144 + cg * 16);
        cp_async16(d + F_QH, qh + g);
        cp_async16(d + F_QL, ql + g);
    }
    cp_commit();

    auto issue_kv = [&](int s0, uint32_t st) {
#pragma unroll
        for (int it = 0; it < 4; it++) {
            int idx = tid + it * 128; // 0..511
            int row = idx >> 3, cg = idx & 7;
            size_t g = (size_t)((s0 + row) * 2 + b) * 3072 + h * 64 + cg * 8;
            uint32_t d = sbase + st + (uint32_t)(row * 144 + cg * 16);
            cp_async16(d + F_KH, qh + g + E_DIM);
            cp_async16(d + F_KL, ql + g + E_DIM);
            cp_async16(d + F_VH, qh + g + 2 * E_DIM);
            cp_async16(d + F_VL, ql + g + 2 * E_DIM);
        }
    };

    issue_kv(0, F_ST0);
    if (tid < 64)
        msk0[tid] = g_mask[tid * B_DIM + b] ? NEG_INF_F : 0.f;
    cp_commit();

    float l[2][2];
    l[0][0] = l[0][1] = l[1][0] = l[1][1] = 0.f;
    float o[2][8][4];
#pragma unroll
    for (int mf = 0; mf < 2; mf++)
#pragma unroll
        for (int nf = 0; nf < 8; nf++)
#pragma unroll
            for (int c = 0; c < 4; c++) o[mf][nf][c] = 0.f;

    for (int c = 0; c < 32; c++) {
        uint32_t st = (c & 1) ? F_ST1 : F_ST0;
        float* mk = (c & 1) ? msk1 : msk0;
        if (c + 1 < 32) {
            issue_kv((c + 1) * 64, ((c + 1) & 1) ? F_ST1 : F_ST0);
            float* mkn = ((c + 1) & 1) ? msk1 : msk0;
            if (tid < 64)
                mkn[tid] = g_mask[((c + 1) * 64 + tid) * B_DIM + b] ? NEG_INF_F : 0.f;
            cp_commit();
            cp_wait<1>();
        } else {
            cp_wait<0>();
        }
        __syncthreads();

        // ---- S = Q K^T (3-pass split), warp computes 32x64 ----
        float acc[2][8][4];
#pragma unroll
        for (int mf = 0; mf < 2; mf++)
#pragma unroll
            for (int nf = 0; nf < 8; nf++)
#pragma unroll
                for (int cc = 0; cc < 4; cc++) acc[mf][nf][cc] = 0.f;

#pragma unroll
        for (int kf = 0; kf < 4; kf++) {
            uint32_t qhi[2][4], qlo[2][4];
#pragma unroll
            for (int mf = 0; mf < 2; mf++) {
                int row = qbase + mf * 16 + (lane & 15);
                int col = kf * 16 + (lane >> 4) * 8;
                uint32_t ad = sbase + (uint32_t)(row * 144 + col * 2);
                ldmatrix_x4(qhi[mf][0], qhi[mf][1], qhi[mf][2], qhi[mf][3], ad + F_QH);
                ldmatrix_x4(qlo[mf][0], qlo[mf][1], qlo[mf][2], qlo[mf][3], ad + F_QL);
            }
#pragma unroll
            for (int np = 0; np < 4; np++) {
                int row = (np * 2 + (lane >> 4)) * 8 + (lane & 7);
                int col = kf * 16 + ((lane >> 3) & 1) * 8;
                uint32_t ad = sbase + st + (uint32_t)(row * 144 + col * 2);
                uint32_t khi[4], klo[4];
                ldmatrix_x4(khi[0], khi[1], khi[2], khi[3], ad + F_KH);
                ldmatrix_x4(klo[0], klo[1], klo[2], klo[3], ad + F_KL);
#pragma unroll
                for (int mf = 0; mf < 2; mf++) {
                    mma_bf16(acc[mf][np * 2],     qhi[mf], khi);
                    mma_bf16(acc[mf][np * 2],     qhi[mf], klo);
                    mma_bf16(acc[mf][np * 2],     qlo[mf], khi);
                    mma_bf16(acc[mf][np * 2 + 1], qhi[mf], khi + 2);
                    mma_bf16(acc[mf][np * 2 + 1], qhi[mf], klo + 2);
                    mma_bf16(acc[mf][np * 2 + 1], qlo[mf], khi + 2);
                }
            }
        }

        // ---- mask + exp (fixed reference m = 0) ----
#pragma unroll
        for (int mf = 0; mf < 2; mf++) {
            float rs1 = 0.f, rs2 = 0.f;
#pragma unroll
            for (int nf = 0; nf < 8; nf++) {
                float2 mv = *(float2*)&mk[nf * 8 + (lane & 3) * 2];
                float p0 = __expf(acc[mf][nf][0] + mv.x);
                float p1 = __expf(acc[mf][nf][1] + mv.y);
                float p2 = __expf(acc[mf][nf][2] + mv.x);
                float p3 = __expf(acc[mf][nf][3] + mv.y);
                acc[mf][nf][0] = p0; acc[mf][nf][1] = p1;
                acc[mf][nf][2] = p2; acc[mf][nf][3] = p3;
                rs1 += p0 + p1;
                rs2 += p2 + p3;
            }
            rs1 += __shfl_xor_sync(0xffffffffu, rs1, 1);
            rs1 += __shfl_xor_sync(0xffffffffu, rs1, 2);
            rs2 += __shfl_xor_sync(0xffffffffu, rs2, 1);
            rs2 += __shfl_xor_sync(0xffffffffu, rs2, 2);
            l[mf][0] += rs1;
            l[mf][1] += rs2;
        }

        // ---- O += P V (3-pass split; P frags built in registers) ----
#pragma unroll
        for (int kf = 0; kf < 4; kf++) {
            uint32_t phi[2][4], plo[2][4];
#pragma unroll
            for (int mf = 0; mf < 2; mf++) {
                split2(acc[mf][2 * kf][0],     acc[mf][2 * kf][1],     phi[mf][0], plo[mf][0]);
                split2(acc[mf][2 * kf][2],     acc[mf][2 * kf][3],     phi[mf][1], plo[mf][1]);
                split2(acc[mf][2 * kf + 1][0], acc[mf][2 * kf + 1][1], phi[mf][2], plo[mf][2]);
                split2(acc[mf][2 * kf + 1][2], acc[mf][2 * kf + 1][3], phi[mf][3], plo[mf][3]);
            }
#pragma unroll
            for (int np = 0; np < 4; np++) {
                int row = kf * 16 + (lane & 15);
                int col = (np * 2 + (lane >> 4)) * 8;
                uint32_t ad = sbase + st + (uint32_t)(row * 144 + col * 2);
                uint32_t vhi[4], vlo[4];
                ldmatrix_x4_trans(vhi[0], vhi[1], vhi[2], vhi[3], ad + F_VH);
                ldmatrix_x4_trans(vlo[0], vlo[1], vlo[2], vlo[3], ad + F_VL);
#pragma unroll
                for (int mf = 0; mf < 2; mf++) {
                    mma_bf16(o[mf][np * 2],     phi[mf], vhi);
                    mma_bf16(o[mf][np * 2],     phi[mf], vlo);
                    mma_bf16(o[mf][np * 2],     plo[mf], vhi);
                    mma_bf16(o[mf][np * 2 + 1], phi[mf], vhi + 2);
                    mma_bf16(o[mf][np * 2 + 1], phi[mf], vlo + 2);
                    mma_bf16(o[mf][np * 2 + 1], plo[mf], vhi + 2);
                }
            }
        }
        __syncthreads();
    }

    // ---- epilogue: normalize, split, write bf16 hi/lo ----
#pragma unroll
    for (int mf = 0; mf < 2; mf++) {
        float inv1 = 1.f / l[mf][0];
        float inv2 = 1.f / l[mf][1];
        int t1 = q0 + qbase + mf * 16 + (lane >> 2);
        int t2 = t1 + 8;
#pragma unroll
        for (int nf = 0; nf < 8; nf++) {
            int d = h * 64 + nf * 8 + (lane & 3) * 2;
            size_t r1 = (size_t)(t1 * 2 + b) * E_DIM + d;
            size_t r2 = (size_t)(t2 * 2 + b) * E_DIM + d;
            uint32_t hw, lw;
            split2(o[mf][nf][0] * inv1, o[mf][nf][1] * inv1, hw, lw);
            *(uint32_t*)(attn_hi + r1) = hw;
            *(uint32_t*)(attn_lo + r1) = lw;
            split2(o[mf][nf][2] * inv2, o[mf][nf][3] * inv2, hw, lw);
            *(uint32_t*)(attn_hi + r2) = hw;
            *(uint32_t*)(attn_lo + r2) = lw;
        }
    }
}

// ===========================================================================
extern "C" void kernel_launch(void* const* d_in, const int* in_sizes, int n_in,
                              void* d_out, int out_size)
{
    const float* x      = (const float*)d_in[0];
    const float* w_in   = (const float*)d_in[1];
    const float* b_in   = (const float*)d_in[2];
    const float* w_out  = (const float*)d_in[3];
    const float* b_out  = (const float*)d_in[4];
    const void*  mask   = d_in[5];
    float* out = (float*)d_out;

    __nv_bfloat16 *x_hi, *x_lo, *win_hi, *win_lo, *wout_hi, *wout_lo;
    __nv_bfloat16 *qkv_hi, *qkv_lo, *attn_hi, *attn_lo;
    cudaGetSymbolAddress((void**)&x_hi, g_x_hi);
    cudaGetSymbolAddress((void**)&x_lo, g_x_lo);
    cudaGetSymbolAddress((void**)&win_hi, g_win_hi);
    cudaGetSymbolAddress((void**)&win_lo, g_win_lo);
    cudaGetSymbolAddress((void**)&wout_hi, g_wout_hi);
    cudaGetSymbolAddress((void**)&wout_lo, g_wout_lo);
    cudaGetSymbolAddress((void**)&qkv_hi, g_qkv_hi);
    cudaGetSymbolAddress((void**)&qkv_lo, g_qkv_lo);
    cudaGetSymbolAddress((void**)&attn_hi, g_attn_hi);
    cudaGetSymbolAddress((void**)&attn_lo, g_attn_lo);

    cudaFuncSetAttribute(gemm_mma2<true>,
                         cudaFuncAttributeMaxDynamicSharedMemorySize, G_TOTAL);
    cudaFuncSetAttribute(gemm_mma2<false>,
                         cudaFuncAttributeMaxDynamicSharedMemorySize, G_TOTAL);
    cudaFuncSetAttribute(flash_mma3,
                         cudaFuncAttributeMaxDynamicSharedMemorySize, F_TOTAL);

    // 0) normalize mask + pre-split inputs
    mask_detect_kernel<<<1, 256>>>((const unsigned char*)mask);
    mask_expand_kernel<<<(MROWS + 255) / 256, 256>>>(mask);
    presplit_kernel<<<(MROWS * E_DIM / 4 + 255) / 256, 256>>>(x, x_hi, x_lo,
                                                              MROWS * E_DIM / 4);
    presplit_kernel<<<(3 * E_DIM * E_DIM / 4 + 255) / 256, 256>>>(
        w_in, win_hi, win_lo, 3 * E_DIM * E_DIM / 4);
    presplit_kernel<<<(E_DIM * E_DIM / 4 + 255) / 256, 256>>>(
        w_out, wout_hi, wout_lo, E_DIM * E_DIM / 4);

    // 1) qkv = x @ W_in^T + b_in  (q columns pre-scaled by 0.125) -> split bf16
    {
        dim3 grid((3 * E_DIM) / 64, MROWS / 128);
        gemm_mma2<true><<<grid, 256, G_TOTAL>>>(x_hi, x_lo, win_hi, win_lo,
                                                b_in, nullptr,
                                                qkv_hi, qkv_lo, 3 * E_DIM, E_DIM);
    }

    // 2) flash attention -> split bf16 attn
    {
        dim3 grid(T_DIM / 128, H_DIM, B_DIM);
        flash_mma3<<<grid, 128, F_TOTAL>>>(qkv_hi, qkv_lo, attn_hi, attn_lo);
    }

    // 3) out = attn @ W_out^T + b_out   [4096 x 1024] fp32
    {
        dim3 grid(E_DIM / 64, MROWS / 128);
        gemm_mma2<false><<<grid, 256, G_TOTAL>>>(attn_hi, attn_lo,
                                                 wout_hi, wout_lo,
                                                 b_out, out,
                                                 nullptr, nullptr, E_DIM, 0);
    }
}

// round 8
// speedup vs baseline: 3.8935x; 1.0060x over previous
#include <cuda_runtime.h>
#include <cuda_bf16.h>
#include <cstdint>
#include <cstddef>

#define T_DIM 2048
#define B_DIM 2
#define E_DIM 1024
#define H_DIM 16
#define MROWS (T_DIM * B_DIM)      // 4096
#define K_DIM 1024
#define NEG_INF_F (-1e24f)

// ---------------------------------------------------------------------------
// Scratch (no cudaMalloc allowed) — all bf16 hi/lo split pairs
// ---------------------------------------------------------------------------
__device__ __nv_bfloat16 g_x_hi[(size_t)MROWS * E_DIM];
__device__ __nv_bfloat16 g_x_lo[(size_t)MROWS * E_DIM];
__device__ __nv_bfloat16 g_win_hi[(size_t)3 * E_DIM * E_DIM];
__device__ __nv_bfloat16 g_win_lo[(size_t)3 * E_DIM * E_DIM];
__device__ __nv_bfloat16 g_wout_hi[(size_t)E_DIM * E_DIM];
__device__ __nv_bfloat16 g_wout_lo[(size_t)E_DIM * E_DIM];
__device__ __nv_bfloat16 g_qkv_hi[(size_t)MROWS * 3 * E_DIM];
__device__ __nv_bfloat16 g_qkv_lo[(size_t)MROWS * 3 * E_DIM];
__device__ __nv_bfloat16 g_attn_hi[(size_t)MROWS * E_DIM];
__device__ __nv_bfloat16 g_attn_lo[(size_t)MROWS * E_DIM];
__device__ int g_mask_mode;
__device__ unsigned char g_mask[MROWS];

// ===========================================================================
// PTX helpers
// ===========================================================================
__device__ __forceinline__ uint32_t smem_u32(const void* p) {
    uint32_t a;
    asm("{ .reg .u64 t; cvta.to.shared.u64 t, %1; cvt.u32.u64 %0, t; }"
        : "=r"(a) : "l"(p));
    return a;
}
__device__ __forceinline__ void ldmatrix_x4(uint32_t& r0, uint32_t& r1,
                                            uint32_t& r2, uint32_t& r3,
                                            uint32_t addr) {
    asm volatile("ldmatrix.sync.aligned.m8n8.x4.shared.b16 {%0,%1,%2,%3}, [%4];"
                 : "=r"(r0), "=r"(r1), "=r"(r2), "=r"(r3) : "r"(addr));
}
__device__ __forceinline__ void ldmatrix_x4_trans(uint32_t& r0, uint32_t& r1,
                                                  uint32_t& r2, uint32_t& r3,
                                                  uint32_t addr) {
    asm volatile("ldmatrix.sync.aligned.m8n8.x4.trans.shared.b16 {%0,%1,%2,%3}, [%4];"
                 : "=r"(r0), "=r"(r1), "=r"(r2), "=r"(r3) : "r"(addr));
}
// NOTE: non-volatile — register-only op, deps carried by constraints, so
// ptxas is free to interleave independent MMAs (critical for latency hiding).
__device__ __forceinline__ void mma_bf16(float* d, const uint32_t* a,
                                         const uint32_t* b) {
    asm("mma.sync.aligned.m16n8k16.row.col.f32.bf16.bf16.f32 "
        "{%0,%1,%2,%3}, {%4,%5,%6,%7}, {%8,%9}, {%0,%1,%2,%3};"
        : "+f"(d[0]), "+f"(d[1]), "+f"(d[2]), "+f"(d[3])
        : "r"(a[0]), "r"(a[1]), "r"(a[2]), "r"(a[3]), "r"(b[0]), "r"(b[1]));
}
__device__ __forceinline__ void cp_async16(uint32_t dst, const void* src) {
    asm volatile("cp.async.cg.shared.global [%0], [%1], 16;" :: "r"(dst), "l"(src));
}
__device__ __forceinline__ void cp_commit() {
    asm volatile("cp.async.commit_group;" ::: "memory");
}
template<int N> __device__ __forceinline__ void cp_wait() {
    asm volatile("cp.async.wait_group %0;" :: "n"(N) : "memory");
}

__device__ __forceinline__ void split2(float x, float y,
                                       uint32_t& hi, uint32_t& lo) {
    __nv_bfloat16 hx = __float2bfloat16(x);
    __nv_bfloat16 hy = __float2bfloat16(y);
    __nv_bfloat16 lx = __float2bfloat16(x - __bfloat162float(hx));
    __nv_bfloat16 ly = __float2bfloat16(y - __bfloat162float(hy));
    __nv_bfloat162 hp = __halves2bfloat162(hx, hy);
    __nv_bfloat162 lp = __halves2bfloat162(lx, ly);
    hi = *(uint32_t*)&hp;
    lo = *(uint32_t*)&lp;
}

// ===========================================================================
// Mask normalization (dtype-agnostic)
// ===========================================================================
__global__ void mask_detect_kernel(const unsigned char* __restrict__ m)
{
    __shared__ int s_nz, s_f32;
    if (threadIdx.x == 0) { s_nz = 0; s_f32 = 0; }
    __syncthreads();
    int nz = 0, f32 = 0;
    for (int i = threadIdx.x; i < MROWS; i += 256) {
        unsigned char v = m[i];
        if ((i & 3) != 0 && v != 0) nz = 1;
        if ((i & 3) == 3 && v == 0x3F) f32 = 1;
    }
    if (nz)  atomicOr(&s_nz, 1);
    if (f32) atomicOr(&s_f32, 1);
    __syncthreads();
    if (threadIdx.x == 0)
        g_mask_mode = s_f32 ? 2 : (s_nz ? 0 : 1);
}

__global__ void mask_expand_kernel(const void* __restrict__ m)
{
    int i = blockIdx.x * 256 + threadIdx.x;
    if (i >= MROWS) return;
    int mode = g_mask_mode;
    unsigned char r;
    if (mode == 0)      r = ((const unsigned char*)m)[i] != 0;
    else if (mode == 1) r = ((const int*)m)[i] != 0;
    else                r = ((const float*)m)[i] != 0.0f;
    g_mask[i] = r;
}

// ===========================================================================
// Pre-split fp32 -> bf16 hi/lo
// ===========================================================================
__global__ void presplit_kernel(const float* __restrict__ src,
                                __nv_bfloat16* __restrict__ hi,
                                __nv_bfloat16* __restrict__ lo, int n4)
{
    int i = blockIdx.x * 256 + threadIdx.x;
    if (i >= n4) return;
    float4 v = ((const float4*)src)[i];
    uint32_t h0, l0, h1, l1;
    split2(v.x, v.y, h0, l0);
    split2(v.z, v.w, h1, l1);
    uint2 hh, ll;
    hh.x = h0; hh.y = h1;
    ll.x = l0; ll.y = l1;
    ((uint2*)hi)[i] = hh;
    ((uint2*)lo)[i] = ll;
}

// ===========================================================================
// 2-stage pipelined split-bf16 HMMA GEMM, pass-major MMA scheduling.
// ===========================================================================
#define GST   55296
#define G_AH  0
#define G_AL  18432
#define G_BH  36864
#define G_BL  46080
#define G_TOTAL (2 * GST)

template<bool SPLIT_OUT>
__global__ __launch_bounds__(256, 2)
void gemm_mma2(const __nv_bfloat16* __restrict__ Ah,
               const __nv_bfloat16* __restrict__ Al,
               const __nv_bfloat16* __restrict__ Bh,
               const __nv_bfloat16* __restrict__ Bl,
               const float* __restrict__ bias,
               float* __restrict__ C,
               __nv_bfloat16* __restrict__ Ch,
               __nv_bfloat16* __restrict__ Cl,
               int N, int scale_n)
{
    extern __shared__ char sm[];
    uint32_t sbase = smem_u32(sm);
    int tid  = threadIdx.x;
    int lane = tid & 31;
    int wid  = tid >> 5;
    int warp_m = wid & 3;
    int warp_n = wid >> 2;
    int m0 = blockIdx.y * 128;
    int n0 = blockIdx.x * 64;

    float acc[2][4][4];
#pragma unroll
    for (int i = 0; i < 2; i++)
#pragma unroll
        for (int j = 0; j < 4; j++)
#pragma unroll
            for (int c = 0; c < 4; c++) acc[i][j][c] = 0.f;

    auto issue = [&](int k0, uint32_t st) {
#pragma unroll
        for (int it = 0; it < 4; it++) {
            int idx = tid + it * 256;
            int row = idx >> 3, cg = idx & 7;
            size_t g = (size_t)(m0 + row) * K_DIM + k0 + cg * 8;
            uint32_t d = sbase + st + (uint32_t)(row * 144 + cg * 16);
            cp_async16(d + G_AH, Ah + g);
            cp_async16(d + G_AL, Al + g);
        }
#pragma unroll
        for (int it = 0; it < 2; it++) {
            int idx = tid + it * 256;
            int row = idx >> 3, cg = idx & 7;
            size_t g = (size_t)(n0 + row) * K_DIM + k0 + cg * 8;
            uint32_t d = sbase + st + (uint32_t)(row * 144 + cg * 16);
            cp_async16(d + G_BH, Bh + g);
            cp_async16(d + G_BL, Bl + g);
        }
    };

    issue(0, 0);
    cp_commit();

    for (int c = 0; c < 16; c++) {
        uint32_t st = (c & 1) ? GST : 0;
        if (c + 1 < 16) {
            issue((c + 1) * 64, ((c + 1) & 1) ? GST : 0);
            cp_commit();
            cp_wait<1>();
        } else {
            cp_wait<0>();
        }
        __syncthreads();

#pragma unroll
        for (int ks = 0; ks < 4; ks++) {
            uint32_t ahi[2][4], alo[2][4];
#pragma unroll
            for (int mf = 0; mf < 2; mf++) {
                int row = warp_m * 32 + mf * 16 + (lane & 15);
                int col = ks * 16 + (lane >> 4) * 8;
                uint32_t ad = sbase + st + (uint32_t)(row * 144 + col * 2);
                ldmatrix_x4(ahi[mf][0], ahi[mf][1], ahi[mf][2], ahi[mf][3], ad + G_AH);
                ldmatrix_x4(alo[mf][0], alo[mf][1], alo[mf][2], alo[mf][3], ad + G_AL);
            }
            uint32_t bhi[4][2], blo[4][2];
#pragma unroll
            for (int np = 0; np < 2; np++) {
                int row = warp_n * 32 + (np * 2 + (lane >> 4)) * 8 + (lane & 7);
                int col = ks * 16 + ((lane >> 3) & 1) * 8;
                uint32_t ad = sbase + st + (uint32_t)(row * 144 + col * 2);
                uint32_t r0, r1, r2, r3;
                ldmatrix_x4(r0, r1, r2, r3, ad + G_BH);
                bhi[np * 2][0] = r0; bhi[np * 2][1] = r1;
                bhi[np * 2 + 1][0] = r2; bhi[np * 2 + 1][1] = r3;
                ldmatrix_x4(r0, r1, r2, r3, ad + G_BL);
                blo[np * 2][0] = r0; blo[np * 2][1] = r1;
                blo[np * 2 + 1][0] = r2; blo[np * 2 + 1][1] = r3;
            }
            // pass-major: same-acc reuse distance = 8
#pragma unroll
            for (int mf = 0; mf < 2; mf++)
#pragma unroll
                for (int nf = 0; nf < 4; nf++)
                    mma_bf16(acc[mf][nf], ahi[mf], bhi[nf]);
#pragma unroll
            for (int mf = 0; mf < 2; mf++)
#pragma unroll
                for (int nf = 0; nf < 4; nf++)
                    mma_bf16(acc[mf][nf], ahi[mf], blo[nf]);
#pragma unroll
            for (int mf = 0; mf < 2; mf++)
#pragma unroll
                for (int nf = 0; nf < 4; nf++)
                    mma_bf16(acc[mf][nf], alo[mf], bhi[nf]);
        }
        __syncthreads();
    }

#pragma unroll
    for (int mf = 0; mf < 2; mf++) {
#pragma unroll
        for (int nf = 0; nf < 4; nf++) {
            int row = m0 + warp_m * 32 + mf * 16 + (lane >> 2);
            int col = n0 + warp_n * 32 + nf * 8 + (lane & 3) * 2;
            float sc = (col < scale_n) ? 0.125f : 1.0f;
            float b0 = bias[col], b1 = bias[col + 1];
            float d0 = (acc[mf][nf][0] + b0) * sc;
            float d1 = (acc[mf][nf][1] + b1) * sc;
            float d2 = (acc[mf][nf][2] + b0) * sc;
            float d3 = (acc[mf][nf][3] + b1) * sc;
            if (SPLIT_OUT) {
                uint32_t hw, lw;
                split2(d0, d1, hw, lw);
                *(uint32_t*)(Ch + (size_t)row * N + col) = hw;
                *(uint32_t*)(Cl + (size_t)row * N + col) = lw;
                split2(d2, d3, hw, lw);
                *(uint32_t*)(Ch + (size_t)(row + 8) * N + col) = hw;
                *(uint32_t*)(Cl + (size_t)(row + 8) * N + col) = lw;
            } else {
                C[(size_t)row * N + col]           = d0;
                C[(size_t)row * N + col + 1]       = d1;
                C[(size_t)(row + 8) * N + col]     = d2;
                C[(size_t)(row + 8) * N + col + 1] = d3;
            }
        }
    }
}

// ===========================================================================
// Flash attention v4: same structure as v3, pass-major MMA scheduling
// (all fragments for a k-step loaded first; same-acc distance = 16).
// ===========================================================================
#define F_QH   0
#define F_QL   18432
#define F_ST0  36864
#define F_ST1  73728
#define F_KH   0
#define F_KL   9216
#define F_VH   18432
#define F_VL   27648
#define F_MSK0 110592
#define F_MSK1 110848
#define F_TOTAL 111104

__global__ __launch_bounds__(128, 2)
void flash_mma4(const __nv_bfloat16* __restrict__ qh,
                const __nv_bfloat16* __restrict__ ql,
                __nv_bfloat16* __restrict__ attn_hi,
                __nv_bfloat16* __restrict__ attn_lo)
{
    extern __shared__ char sm[];
    uint32_t sbase = smem_u32(sm);
    float* msk0 = (float*)(sm + F_MSK0);
    float* msk1 = (float*)(sm + F_MSK1);
    int tid = threadIdx.x;
    int lane = tid & 31;
    int w = tid >> 5;
    int b = blockIdx.z;
    int h = blockIdx.y;
    int q0 = blockIdx.x * 128;
    int qbase = w * 32;

#pragma unroll
    for (int it = 0; it < 8; it++) {
        int idx = tid + it * 128;
        int row = idx >> 3, cg = idx & 7;
        size_t g = (size_t)((q0 + row) * 2 + b) * 3072 + h * 64 + cg * 8;
        uint32_t d = sbase + (uint32_t)(row * 144 + cg * 16);
        cp_async16(d + F_QH, qh + g);
        cp_async16(d + F_QL, ql + g);
    }
    cp_commit();

    auto issue_kv = [&](int s0, uint32_t st) {
#pragma unroll
        for (int it = 0; it < 4; it++) {
            int idx = tid + it * 128;
            int row = idx >> 3, cg = idx & 7;
            size_t g = (size_t)((s0 + row) * 2 + b) * 3072 + h * 64 + cg * 8;
            uint32_t d = sbase + st + (uint32_t)(row * 144 + cg * 16);
            cp_async16(d + F_KH, qh + g + E_DIM);
            cp_async16(d + F_KL, ql + g + E_DIM);
            cp_async16(d + F_VH, qh + g + 2 * E_DIM);
            cp_async16(d + F_VL, ql + g + 2 * E_DIM);
        }
    };

    issue_kv(0, F_ST0);
    if (tid < 64)
        msk0[tid] = g_mask[tid * B_DIM + b] ? NEG_INF_F : 0.f;
    cp_commit();

    float l[2][2];
    l[0][0] = l[0][1] = l[1][0] = l[1][1] = 0.f;
    float o[2][8][4];
#pragma unroll
    for (int mf = 0; mf < 2; mf++)
#pragma unroll
        for (int nf = 0; nf < 8; nf++)
#pragma unroll
            for (int c = 0; c < 4; c++) o[mf][nf][c] = 0.f;

    for (int c = 0; c < 32; c++) {
        uint32_t st = (c & 1) ? F_ST1 : F_ST0;
        float* mk = (c & 1) ? msk1 : msk0;
        if (c + 1 < 32) {
            issue_kv((c + 1) * 64, ((c + 1) & 1) ? F_ST1 : F_ST0);
            float* mkn = ((c + 1) & 1) ? msk1 : msk0;
            if (tid < 64)
                mkn[tid] = g_mask[((c + 1) * 64 + tid) * B_DIM + b] ? NEG_INF_F : 0.f;
            cp_commit();
            cp_wait<1>();
        } else {
            cp_wait<0>();
        }
        __syncthreads();

        // ---- S = Q K^T, pass-major ----
        float acc[2][8][4];
#pragma unroll
        for (int mf = 0; mf < 2; mf++)
#pragma unroll
            for (int nf = 0; nf < 8; nf++)
#pragma unroll
                for (int cc = 0; cc < 4; cc++) acc[mf][nf][cc] = 0.f;

#pragma unroll
        for (int kf = 0; kf < 4; kf++) {
            uint32_t qhi[2][4], qlo[2][4];
#pragma unroll
            for (int mf = 0; mf < 2; mf++) {
                int row = qbase + mf * 16 + (lane & 15);
                int col = kf * 16 + (lane >> 4) * 8;
                uint32_t ad = sbase + (uint32_t)(row * 144 + col * 2);
                ldmatrix_x4(qhi[mf][0], qhi[mf][1], qhi[mf][2], qhi[mf][3], ad + F_QH);
                ldmatrix_x4(qlo[mf][0], qlo[mf][1], qlo[mf][2], qlo[mf][3], ad + F_QL);
            }
            uint32_t khi[4][4], klo[4][4];
#pragma unroll
            for (int np = 0; np < 4; np++) {
                int row = (np * 2 + (lane >> 4)) * 8 + (lane & 7);
                int col = kf * 16 + ((lane >> 3) & 1) * 8;
                uint32_t ad = sbase + st + (uint32_t)(row * 144 + col * 2);
                ldmatrix_x4(khi[np][0], khi[np][1], khi[np][2], khi[np][3], ad + F_KH);
                ldmatrix_x4(klo[np][0], klo[np][1], klo[np][2], klo[np][3], ad + F_KL);
            }
            // pass hh
#pragma unroll
            for (int mf = 0; mf < 2; mf++)
#pragma unroll
                for (int np = 0; np < 4; np++) {
                    mma_bf16(acc[mf][np * 2],     qhi[mf], khi[np]);
                    mma_bf16(acc[mf][np * 2 + 1], qhi[mf], khi[np] + 2);
                }
            // pass hl
#pragma unroll
            for (int mf = 0; mf < 2; mf++)
#pragma unroll
                for (int np = 0; np < 4; np++) {
                    mma_bf16(acc[mf][np * 2],     qhi[mf], klo[np]);
                    mma_bf16(acc[mf][np * 2 + 1], qhi[mf], klo[np] + 2);
                }
            // pass lh
#pragma unroll
            for (int mf = 0; mf < 2; mf++)
#pragma unroll
                for (int np = 0; np < 4; np++) {
                    mma_bf16(acc[mf][np * 2],     qlo[mf], khi[np]);
                    mma_bf16(acc[mf][np * 2 + 1], qlo[mf], khi[np] + 2);
                }
        }

        // ---- mask + exp (fixed reference m = 0) ----
#pragma unroll
        for (int mf = 0; mf < 2; mf++) {
            float rs1 = 0.f, rs2 = 0.f;
#pragma unroll
            for (int nf = 0; nf < 8; nf++) {
                float2 mv = *(float2*)&mk[nf * 8 + (lane & 3) * 2];
                float p0 = __expf(acc[mf][nf][0] + mv.x);
                float p1 = __expf(acc[mf][nf][1] + mv.y);
                float p2 = __expf(acc[mf][nf][2] + mv.x);
                float p3 = __expf(acc[mf][nf][3] + mv.y);
                acc[mf][nf][0] = p0; acc[mf][nf][1] = p1;
                acc[mf][nf][2] = p2; acc[mf][nf][3] = p3;
                rs1 += p0 + p1;
                rs2 += p2 + p3;
            }
            rs1 += __shfl_xor_sync(0xffffffffu, rs1, 1);
            rs1 += __shfl_xor_sync(0xffffffffu, rs1, 2);
            rs2 += __shfl_xor_sync(0xffffffffu, rs2, 1);
            rs2 += __shfl_xor_sync(0xffffffffu, rs2, 2);
            l[mf][0] += rs1;
            l[mf][1] += rs2;
        }

        // ---- O += P V, pass-major ----
#pragma unroll
        for (int kf = 0; kf < 4; kf++) {
            uint32_t phi[2][4], plo[2][4];
#pragma unroll
            for (int mf = 0; mf < 2; mf++) {
                split2(acc[mf][2 * kf][0],     acc[mf][2 * kf][1],     phi[mf][0], plo[mf][0]);
                split2(acc[mf][2 * kf][2],     acc[mf][2 * kf][3],     phi[mf][1], plo[mf][1]);
                split2(acc[mf][2 * kf + 1][0], acc[mf][2 * kf + 1][1], phi[mf][2], plo[mf][2]);
                split2(acc[mf][2 * kf + 1][2], acc[mf][2 * kf + 1][3], phi[mf][3], plo[mf][3]);
            }
            uint32_t vhi[4][4], vlo[4][4];
#pragma unroll
            for (int np = 0; np < 4; np++) {
                int row = kf * 16 + (lane & 15);
                int col = (np * 2 + (lane >> 4)) * 8;
                uint32_t ad = sbase + st + (uint32_t)(row * 144 + col * 2);
                ldmatrix_x4_trans(vhi[np][0], vhi[np][1], vhi[np][2], vhi[np][3], ad + F_VH);
                ldmatrix_x4_trans(vlo[np][0], vlo[np][1], vlo[np][2], vlo[np][3], ad + F_VL);
            }
            // pass hh
#pragma unroll
            for (int mf = 0; mf < 2; mf++)
#pragma unroll
                for (int np = 0; np < 4; np++) {
                    mma_bf16(o[mf][np * 2],     phi[mf], vhi[np]);
                    mma_bf16(o[mf][np * 2 + 1], phi[mf], vhi[np] + 2);
                }
            // pass hl
#pragma unroll
            for (int mf = 0; mf < 2; mf++)
#pragma unroll
                for (int np = 0; np < 4; np++) {
                    mma_bf16(o[mf][np * 2],     phi[mf], vlo[np]);
                    mma_bf16(o[mf][np * 2 + 1], phi[mf], vlo[np] + 2);
                }
            // pass lh
#pragma unroll
            for (int mf = 0; mf < 2; mf++)
#pragma unroll
                for (int np = 0; np < 4; np++) {
                    mma_bf16(o[mf][np * 2],     plo[mf], vhi[np]);
                    mma_bf16(o[mf][np * 2 + 1], plo[mf], vhi[np] + 2);
                }
        }
        __syncthreads();
    }

    // ---- epilogue ----
#pragma unroll
    for (int mf = 0; mf < 2; mf++) {
        float inv1 = 1.f / l[mf][0];
        float inv2 = 1.f / l[mf][1];
        int t1 = q0 + qbase + mf * 16 + (lane >> 2);
        int t2 = t1 + 8;
#pragma unroll
        for (int nf = 0; nf < 8; nf++) {
            int d = h * 64 + nf * 8 + (lane & 3) * 2;
            size_t r1 = (size_t)(t1 * 2 + b) * E_DIM + d;
            size_t r2 = (size_t)(t2 * 2 + b) * E_DIM + d;
            uint32_t hw, lw;
            split2(o[mf][nf][0] * inv1, o[mf][nf][1] * inv1, hw, lw);
            *(uint32_t*)(attn_hi + r1) = hw;
            *(uint32_t*)(attn_lo + r1) = lw;
            split2(o[mf][nf][2] * inv2, o[mf][nf][3] * inv2, hw, lw);
            *(uint32_t*)(attn_hi + r2) = hw;
            *(uint32_t*)(attn_lo + r2) = lw;
        }
    }
}

// ===========================================================================
extern "C" void kernel_launch(void* const* d_in, const int* in_sizes, int n_in,
                              void* d_out, int out_size)
{
    const float* x      = (const float*)d_in[0];
    const float* w_in   = (const float*)d_in[1];
    const float* b_in   = (const float*)d_in[2];
    const float* w_out  = (const float*)d_in[3];
    const float* b_out  = (const float*)d_in[4];
    const void*  mask   = d_in[5];
    float* out = (float*)d_out;

    __nv_bfloat16 *x_hi, *x_lo, *win_hi, *win_lo, *wout_hi, *wout_lo;
    __nv_bfloat16 *qkv_hi, *qkv_lo, *attn_hi, *attn_lo;
    cudaGetSymbolAddress((void**)&x_hi, g_x_hi);
    cudaGetSymbolAddress((void**)&x_lo, g_x_lo);
    cudaGetSymbolAddress((void**)&win_hi, g_win_hi);
    cudaGetSymbolAddress((void**)&win_lo, g_win_lo);
    cudaGetSymbolAddress((void**)&wout_hi, g_wout_hi);
    cudaGetSymbolAddress((void**)&wout_lo, g_wout_lo);
    cudaGetSymbolAddress((void**)&qkv_hi, g_qkv_hi);
    cudaGetSymbolAddress((void**)&qkv_lo, g_qkv_lo);
    cudaGetSymbolAddress((void**)&attn_hi, g_attn_hi);
    cudaGetSymbolAddress((void**)&attn_lo, g_attn_lo);

    cudaFuncSetAttribute(gemm_mma2<true>,
                         cudaFuncAttributeMaxDynamicSharedMemorySize, G_TOTAL);
    cudaFuncSetAttribute(gemm_mma2<false>,
                         cudaFuncAttributeMaxDynamicSharedMemorySize, G_TOTAL);
    cudaFuncSetAttribute(flash_mma4,
                         cudaFuncAttributeMaxDynamicSharedMemorySize, F_TOTAL);

    // 0) normalize mask + pre-split inputs
    mask_detect_kernel<<<1, 256>>>((const unsigned char*)mask);
    mask_expand_kernel<<<(MROWS + 255) / 256, 256>>>(mask);
    presplit_kernel<<<(MROWS * E_DIM / 4 + 255) / 256, 256>>>(x, x_hi, x_lo,
                                                              MROWS * E_DIM / 4);
    presplit_kernel<<<(3 * E_DIM * E_DIM / 4 + 255) / 256, 256>>>(
        w_in, win_hi, win_lo, 3 * E_DIM * E_DIM / 4);
    presplit_kernel<<<(E_DIM * E_DIM / 4 + 255) / 256, 256>>>(
        w_out, wout_hi, wout_lo, E_DIM * E_DIM / 4);

    // 1) qkv = x @ W_in^T + b_in  (q pre-scaled by 0.125) -> split bf16
    {
        dim3 grid((3 * E_DIM) / 64, MROWS / 128);
        gemm_mma2<true><<<grid, 256, G_TOTAL>>>(x_hi, x_lo, win_hi, win_lo,
                                                b_in, nullptr,
                                                qkv_hi, qkv_lo, 3 * E_DIM, E_DIM);
    }

    // 2) flash attention -> split bf16 attn
    {
        dim3 grid(T_DIM / 128, H_DIM, B_DIM);
        flash_mma4<<<grid, 128, F_TOTAL>>>(qkv_hi, qkv_lo, attn_hi, attn_lo);
    }

    // 3) out = attn @ W_out^T + b_out   [4096 x 1024] fp32
    {
        dim3 grid(E_DIM / 64, MROWS / 128);
        gemm_mma2<false><<<grid, 256, G_TOTAL>>>(attn_hi, attn_lo,
                                                 wout_hi, wout_lo,
                                                 b_out, out,
                                                 nullptr, nullptr, E_DIM, 0);
    }
}

// round 9
// speedup vs baseline: 4.7603x; 1.2226x over previous
#include <cuda_runtime.h>
#include <cuda_bf16.h>
#include <cstdint>
#include <cstddef>

#define T_DIM 2048
#define B_DIM 2
#define E_DIM 1024
#define H_DIM 16
#define MROWS (T_DIM * B_DIM)      // 4096
#define K_DIM 1024
#define NEG_INF_F (-1e24f)

// ---------------------------------------------------------------------------
// Scratch (no cudaMalloc allowed)
// ---------------------------------------------------------------------------
__device__ __nv_bfloat16 g_x_hi[(size_t)MROWS * E_DIM];
__device__ __nv_bfloat16 g_x_lo[(size_t)MROWS * E_DIM];
__device__ __nv_bfloat16 g_win_hi[(size_t)3 * E_DIM * E_DIM];
__device__ __nv_bfloat16 g_win_lo[(size_t)3 * E_DIM * E_DIM];
__device__ __nv_bfloat16 g_wout_hi[(size_t)E_DIM * E_DIM];
__device__ __nv_bfloat16 g_wout_lo[(size_t)E_DIM * E_DIM];
__device__ __nv_bfloat16 g_qkv_hi[(size_t)MROWS * 3 * E_DIM];
__device__ __nv_bfloat16 g_qkv_lo[(size_t)MROWS * 3 * E_DIM];
__device__ __nv_bfloat16 g_attn_hi[(size_t)MROWS * E_DIM];
__device__ __nv_bfloat16 g_attn_lo[(size_t)MROWS * E_DIM];
__device__ int g_mask_mode;
__device__ unsigned char g_mask[MROWS];
// key compaction: per batch, indices of UNMASKED keys + count + pad mask
__device__ int   g_kidx[B_DIM * T_DIM];
__device__ int   g_kcount[B_DIM];
__device__ float g_kmask[B_DIM * T_DIM];

// ===========================================================================
// PTX helpers
// ===========================================================================
__device__ __forceinline__ uint32_t smem_u32(const void* p) {
    uint32_t a;
    asm("{ .reg .u64 t; cvta.to.shared.u64 t, %1; cvt.u32.u64 %0, t; }"
        : "=r"(a) : "l"(p));
    return a;
}
__device__ __forceinline__ void ldmatrix_x4(uint32_t& r0, uint32_t& r1,
                                            uint32_t& r2, uint32_t& r3,
                                            uint32_t addr) {
    asm volatile("ldmatrix.sync.aligned.m8n8.x4.shared.b16 {%0,%1,%2,%3}, [%4];"
                 : "=r"(r0), "=r"(r1), "=r"(r2), "=r"(r3) : "r"(addr));
}
__device__ __forceinline__ void ldmatrix_x4_trans(uint32_t& r0, uint32_t& r1,
                                                  uint32_t& r2, uint32_t& r3,
                                                  uint32_t addr) {
    asm volatile("ldmatrix.sync.aligned.m8n8.x4.trans.shared.b16 {%0,%1,%2,%3}, [%4];"
                 : "=r"(r0), "=r"(r1), "=r"(r2), "=r"(r3) : "r"(addr));
}
__device__ __forceinline__ void mma_bf16(float* d, const uint32_t* a,
                                         const uint32_t* b) {
    asm("mma.sync.aligned.m16n8k16.row.col.f32.bf16.bf16.f32 "
        "{%0,%1,%2,%3}, {%4,%5,%6,%7}, {%8,%9}, {%0,%1,%2,%3};"
        : "+f"(d[0]), "+f"(d[1]), "+f"(d[2]), "+f"(d[3])
        : "r"(a[0]), "r"(a[1]), "r"(a[2]), "r"(a[3]), "r"(b[0]), "r"(b[1]));
}
__device__ __forceinline__ void cp_async16(uint32_t dst, const void* src) {
    asm volatile("cp.async.cg.shared.global [%0], [%1], 16;" :: "r"(dst), "l"(src));
}
__device__ __forceinline__ void cp_commit() {
    asm volatile("cp.async.commit_group;" ::: "memory");
}
template<int N> __device__ __forceinline__ void cp_wait() {
    asm volatile("cp.async.wait_group %0;" :: "n"(N) : "memory");
}

__device__ __forceinline__ void split2(float x, float y,
                                       uint32_t& hi, uint32_t& lo) {
    __nv_bfloat16 hx = __float2bfloat16(x);
    __nv_bfloat16 hy = __float2bfloat16(y);
    __nv_bfloat16 lx = __float2bfloat16(x - __bfloat162float(hx));
    __nv_bfloat16 ly = __float2bfloat16(y - __bfloat162float(hy));
    __nv_bfloat162 hp = __halves2bfloat162(hx, hy);
    __nv_bfloat162 lp = __halves2bfloat162(lx, ly);
    hi = *(uint32_t*)&hp;
    lo = *(uint32_t*)&lp;
}

// ===========================================================================
// Mask normalization (dtype-agnostic)
// ===========================================================================
__global__ void mask_detect_kernel(const unsigned char* __restrict__ m)
{
    __shared__ int s_nz, s_f32;
    if (threadIdx.x == 0) { s_nz = 0; s_f32 = 0; }
    __syncthreads();
    int nz = 0, f32 = 0;
    for (int i = threadIdx.x; i < MROWS; i += 256) {
        unsigned char v = m[i];
        if ((i & 3) != 0 && v != 0) nz = 1;
        if ((i & 3) == 3 && v == 0x3F) f32 = 1;
    }
    if (nz)  atomicOr(&s_nz, 1);
    if (f32) atomicOr(&s_f32, 1);
    __syncthreads();
    if (threadIdx.x == 0)
        g_mask_mode = s_f32 ? 2 : (s_nz ? 0 : 1);
}

__global__ void mask_expand_kernel(const void* __restrict__ m)
{
    int i = blockIdx.x * 256 + threadIdx.x;
    if (i >= MROWS) return;
    int mode = g_mask_mode;
    unsigned char r;
    if (mode == 0)      r = ((const unsigned char*)m)[i] != 0;
    else if (mode == 1) r = ((const int*)m)[i] != 0;
    else                r = ((const float*)m)[i] != 0.0f;
    g_mask[i] = r;
}

// ===========================================================================
// Key compaction: per batch, list of unmasked key indices (warp ballot scan).
// One block, 64 threads: warp w handles batch w.
// ===========================================================================
__global__ void mask_compact_kernel()
{
    int b = threadIdx.x >> 5;
    int lane = threadIdx.x & 31;
    if (b >= B_DIM) return;
    int base = 0;
    for (int j0 = 0; j0 < T_DIM; j0 += 32) {
        int t = j0 + lane;
        int keep = g_mask[t * B_DIM + b] ? 0 : 1;
        unsigned bal = __ballot_sync(0xffffffffu, keep);
        int pre = __popc(bal & ((1u << lane) - 1));
        if (keep) g_kidx[b * T_DIM + base + pre] = t;
        base += __popc(bal);
    }
    if (lane == 0) g_kcount[b] = base;
    // pad index list to tile boundary; write additive pad mask
    int padded = (base + 63) & ~63;
    for (int j = base + lane; j < padded; j += 32)
        g_kidx[b * T_DIM + j] = 0;
    for (int j = lane; j < T_DIM; j += 32)
        g_kmask[b * T_DIM + j] = (j < base) ? 0.f : NEG_INF_F;
}

// ===========================================================================
// Pre-split fp32 -> bf16 hi/lo
// ===========================================================================
__global__ void presplit_kernel(const float* __restrict__ src,
                                __nv_bfloat16* __restrict__ hi,
                                __nv_bfloat16* __restrict__ lo, int n4)
{
    int i = blockIdx.x * 256 + threadIdx.x;
    if (i >= n4) return;
    float4 v = ((const float4*)src)[i];
    uint32_t h0, l0, h1, l1;
    split2(v.x, v.y, h0, l0);
    split2(v.z, v.w, h1, l1);
    uint2 hh, ll;
    hh.x = h0; hh.y = h1;
    ll.x = l0; ll.y = l1;
    ((uint2*)hi)[i] = hh;
    ((uint2*)lo)[i] = ll;
}

// ===========================================================================
// 2-stage pipelined split-bf16 HMMA GEMM (unchanged from round 8)
// ===========================================================================
#define GST   55296
#define G_AH  0
#define G_AL  18432
#define G_BH  36864
#define G_BL  46080
#define G_TOTAL (2 * GST)

template<bool SPLIT_OUT>
__global__ __launch_bounds__(256, 2)
void gemm_mma2(const __nv_bfloat16* __restrict__ Ah,
               const __nv_bfloat16* __restrict__ Al,
               const __nv_bfloat16* __restrict__ Bh,
               const __nv_bfloat16* __restrict__ Bl,
               const float* __restrict__ bias,
               float* __restrict__ C,
               __nv_bfloat16* __restrict__ Ch,
               __nv_bfloat16* __restrict__ Cl,
               int N, int scale_n)
{
    extern __shared__ char sm[];
    uint32_t sbase = smem_u32(sm);
    int tid  = threadIdx.x;
    int lane = tid & 31;
    int wid  = tid >> 5;
    int warp_m = wid & 3;
    int warp_n = wid >> 2;
    int m0 = blockIdx.y * 128;
    int n0 = blockIdx.x * 64;

    float acc[2][4][4];
#pragma unroll
    for (int i = 0; i < 2; i++)
#pragma unroll
        for (int j = 0; j < 4; j++)
#pragma unroll
            for (int c = 0; c < 4; c++) acc[i][j][c] = 0.f;

    auto issue = [&](int k0, uint32_t st) {
#pragma unroll
        for (int it = 0; it < 4; it++) {
            int idx = tid + it * 256;
            int row = idx >> 3, cg = idx & 7;
            size_t g = (size_t)(m0 + row) * K_DIM + k0 + cg * 8;
            uint32_t d = sbase + st + (uint32_t)(row * 144 + cg * 16);
            cp_async16(d + G_AH, Ah + g);
            cp_async16(d + G_AL, Al + g);
        }
#pragma unroll
        for (int it = 0; it < 2; it++) {
            int idx = tid + it * 256;
            int row = idx >> 3, cg = idx & 7;
            size_t g = (size_t)(n0 + row) * K_DIM + k0 + cg * 8;
            uint32_t d = sbase + st + (uint32_t)(row * 144 + cg * 16);
            cp_async16(d + G_BH, Bh + g);
            cp_async16(d + G_BL, Bl + g);
        }
    };

    issue(0, 0);
    cp_commit();

    for (int c = 0; c < 16; c++) {
        uint32_t st = (c & 1) ? GST : 0;
        if (c + 1 < 16) {
            issue((c + 1) * 64, ((c + 1) & 1) ? GST : 0);
            cp_commit();
            cp_wait<1>();
        } else {
            cp_wait<0>();
        }
        __syncthreads();

#pragma unroll
        for (int ks = 0; ks < 4; ks++) {
            uint32_t ahi[2][4], alo[2][4];
#pragma unroll
            for (int mf = 0; mf < 2; mf++) {
                int row = warp_m * 32 + mf * 16 + (lane & 15);
                int col = ks * 16 + (lane >> 4) * 8;
                uint32_t ad = sbase + st + (uint32_t)(row * 144 + col * 2);
                ldmatrix_x4(ahi[mf][0], ahi[mf][1], ahi[mf][2], ahi[mf][3], ad + G_AH);
                ldmatrix_x4(alo[mf][0], alo[mf][1], alo[mf][2], alo[mf][3], ad + G_AL);
            }
            uint32_t bhi[4][2], blo[4][2];
#pragma unroll
            for (int np = 0; np < 2; np++) {
                int row = warp_n * 32 + (np * 2 + (lane >> 4)) * 8 + (lane & 7);
                int col = ks * 16 + ((lane >> 3) & 1) * 8;
                uint32_t ad = sbase + st + (uint32_t)(row * 144 + col * 2);
                uint32_t r0, r1, r2, r3;
                ldmatrix_x4(r0, r1, r2, r3, ad + G_BH);
                bhi[np * 2][0] = r0; bhi[np * 2][1] = r1;
                bhi[np * 2 + 1][0] = r2; bhi[np * 2 + 1][1] = r3;
                ldmatrix_x4(r0, r1, r2, r3, ad + G_BL);
                blo[np * 2][0] = r0; blo[np * 2][1] = r1;
                blo[np * 2 + 1][0] = r2; blo[np * 2 + 1][1] = r3;
            }
#pragma unroll
            for (int mf = 0; mf < 2; mf++)
#pragma unroll
                for (int nf = 0; nf < 4; nf++)
                    mma_bf16(acc[mf][nf], ahi[mf], bhi[nf]);
#pragma unroll
            for (int mf = 0; mf < 2; mf++)
#pragma unroll
                for (int nf = 0; nf < 4; nf++)
                    mma_bf16(acc[mf][nf], ahi[mf], blo[nf]);
#pragma unroll
            for (int mf = 0; mf < 2; mf++)
#pragma unroll
                for (int nf = 0; nf < 4; nf++)
                    mma_bf16(acc[mf][nf], alo[mf], bhi[nf]);
        }
        __syncthreads();
    }

#pragma unroll
    for (int mf = 0; mf < 2; mf++) {
#pragma unroll
        for (int nf = 0; nf < 4; nf++) {
            int row = m0 + warp_m * 32 + mf * 16 + (lane >> 2);
            int col = n0 + warp_n * 32 + nf * 8 + (lane & 3) * 2;
            float sc = (col < scale_n) ? 0.125f : 1.0f;
            float b0 = bias[col], b1 = bias[col + 1];
            float d0 = (acc[mf][nf][0] + b0) * sc;
            float d1 = (acc[mf][nf][1] + b1) * sc;
            float d2 = (acc[mf][nf][2] + b0) * sc;
            float d3 = (acc[mf][nf][3] + b1) * sc;
            if (SPLIT_OUT) {
                uint32_t hw, lw;
                split2(d0, d1, hw, lw);
                *(uint32_t*)(Ch + (size_t)row * N + col) = hw;
                *(uint32_t*)(Cl + (size_t)row * N + col) = lw;
                split2(d2, d3, hw, lw);
                *(uint32_t*)(Ch + (size_t)(row + 8) * N + col) = hw;
                *(uint32_t*)(Cl + (size_t)(row + 8) * N + col) = lw;
            } else {
                C[(size_t)row * N + col]           = d0;
                C[(size_t)row * N + col + 1]       = d1;
                C[(size_t)(row + 8) * N + col]     = d2;
                C[(size_t)(row + 8) * N + col + 1] = d3;
            }
        }
    }
}

// ===========================================================================
// Flash attention v5: key-compacted. Only unmasked K/V rows are gathered;
// s-loop runs ceil(count/64) tiles (~16 instead of 32). Pad columns get
// additive NEG_INF from g_kmask (tail tile only).
// ===========================================================================
#define F_QH   0
#define F_QL   18432
#define F_ST0  36864
#define F_ST1  73728
#define F_KH   0
#define F_KL   9216
#define F_VH   18432
#define F_VL   27648
#define F_MSK0 110592
#define F_MSK1 110848
#define F_TOTAL 111104

__global__ __launch_bounds__(128, 2)
void flash_mma5(const __nv_bfloat16* __restrict__ qh,
                const __nv_bfloat16* __restrict__ ql,
                __nv_bfloat16* __restrict__ attn_hi,
                __nv_bfloat16* __restrict__ attn_lo)
{
    extern __shared__ char sm[];
    uint32_t sbase = smem_u32(sm);
    float* msk0 = (float*)(sm + F_MSK0);
    float* msk1 = (float*)(sm + F_MSK1);
    int tid = threadIdx.x;
    int lane = tid & 31;
    int w = tid >> 5;
    int b = blockIdx.z;
    int h = blockIdx.y;
    int q0 = blockIdx.x * 128;
    int qbase = w * 32;

    int cnt = g_kcount[b];
    int ntiles = (cnt + 63) >> 6;

#pragma unroll
    for (int it = 0; it < 8; it++) {
        int idx = tid + it * 128;
        int row = idx >> 3, cg = idx & 7;
        size_t g = (size_t)((q0 + row) * 2 + b) * 3072 + h * 64 + cg * 8;
        uint32_t d = sbase + (uint32_t)(row * 144 + cg * 16);
        cp_async16(d + F_QH, qh + g);
        cp_async16(d + F_QL, ql + g);
    }
    cp_commit();

    auto issue_kv = [&](int s0, uint32_t st) {
#pragma unroll
        for (int it = 0; it < 4; it++) {
            int idx = tid + it * 128;
            int row = idx >> 3, cg = idx & 7;
            int t = g_kidx[b * T_DIM + s0 + row];      // gather unmasked key
            size_t g = (size_t)(t * 2 + b) * 3072 + h * 64 + cg * 8;
            uint32_t d = sbase + st + (uint32_t)(row * 144 + cg * 16);
            cp_async16(d + F_KH, qh + g + E_DIM);
            cp_async16(d + F_KL, ql + g + E_DIM);
            cp_async16(d + F_VH, qh + g + 2 * E_DIM);
            cp_async16(d + F_VL, ql + g + 2 * E_DIM);
        }
    };

    issue_kv(0, F_ST0);
    if (tid < 64)
        msk0[tid] = g_kmask[b * T_DIM + tid];
    cp_commit();

    float l[2][2];
    l[0][0] = l[0][1] = l[1][0] = l[1][1] = 0.f;
    float o[2][8][4];
#pragma unroll
    for (int mf = 0; mf < 2; mf++)
#pragma unroll
        for (int nf = 0; nf < 8; nf++)
#pragma unroll
            for (int c = 0; c < 4; c++) o[mf][nf][c] = 0.f;

    for (int c = 0; c < ntiles; c++) {
        uint32_t st = (c & 1) ? F_ST1 : F_ST0;
        float* mk = (c & 1) ? msk1 : msk0;
        if (c + 1 < ntiles) {
            issue_kv((c + 1) * 64, ((c + 1) & 1) ? F_ST1 : F_ST0);
            float* mkn = ((c + 1) & 1) ? msk1 : msk0;
            if (tid < 64)
                mkn[tid] = g_kmask[b * T_DIM + (c + 1) * 64 + tid];
            cp_commit();
            cp_wait<1>();
        } else {
            cp_wait<0>();
        }
        __syncthreads();

        // ---- S = Q K^T, pass-major ----
        float acc[2][8][4];
#pragma unroll
        for (int mf = 0; mf < 2; mf++)
#pragma unroll
            for (int nf = 0; nf < 8; nf++)
#pragma unroll
                for (int cc = 0; cc < 4; cc++) acc[mf][nf][cc] = 0.f;

#pragma unroll
        for (int kf = 0; kf < 4; kf++) {
            uint32_t qhi[2][4], qlo[2][4];
#pragma unroll
            for (int mf = 0; mf < 2; mf++) {
                int row = qbase + mf * 16 + (lane & 15);
                int col = kf * 16 + (lane >> 4) * 8;
                uint32_t ad = sbase + (uint32_t)(row * 144 + col * 2);
                ldmatrix_x4(qhi[mf][0], qhi[mf][1], qhi[mf][2], qhi[mf][3], ad + F_QH);
                ldmatrix_x4(qlo[mf][0], qlo[mf][1], qlo[mf][2], qlo[mf][3], ad + F_QL);
            }
            uint32_t khi[4][4], klo[4][4];
#pragma unroll
            for (int np = 0; np < 4; np++) {
                int row = (np * 2 + (lane >> 4)) * 8 + (lane & 7);
                int col = kf * 16 + ((lane >> 3) & 1) * 8;
                uint32_t ad = sbase + st + (uint32_t)(row * 144 + col * 2);
                ldmatrix_x4(khi[np][0], khi[np][1], khi[np][2], khi[np][3], ad + F_KH);
                ldmatrix_x4(klo[np][0], klo[np][1], klo[np][2], klo[np][3], ad + F_KL);
            }
#pragma unroll
            for (int mf = 0; mf < 2; mf++)
#pragma unroll
                for (int np = 0; np < 4; np++) {
                    mma_bf16(acc[mf][np * 2],     qhi[mf], khi[np]);
                    mma_bf16(acc[mf][np * 2 + 1], qhi[mf], khi[np] + 2);
                }
#pragma unroll
            for (int mf = 0; mf < 2; mf++)
#pragma unroll
                for (int np = 0; np < 4; np++) {
                    mma_bf16(acc[mf][np * 2],     qhi[mf], klo[np]);
                    mma_bf16(acc[mf][np * 2 + 1], qhi[mf], klo[np] + 2);
                }
#pragma unroll
            for (int mf = 0; mf < 2; mf++)
#pragma unroll
                for (int np = 0; np < 4; np++) {
                    mma_bf16(acc[mf][np * 2],     qlo[mf], khi[np]);
                    mma_bf16(acc[mf][np * 2 + 1], qlo[mf], khi[np] + 2);
                }
        }

        // ---- pad-mask + exp (fixed reference m = 0) ----
#pragma unroll
        for (int mf = 0; mf < 2; mf++) {
            float rs1 = 0.f, rs2 = 0.f;
#pragma unroll
            for (int nf = 0; nf < 8; nf++) {
                float2 mv = *(float2*)&mk[nf * 8 + (lane & 3) * 2];
                float p0 = __expf(acc[mf][nf][0] + mv.x);
                float p1 = __expf(acc[mf][nf][1] + mv.y);
                float p2 = __expf(acc[mf][nf][2] + mv.x);
                float p3 = __expf(acc[mf][nf][3] + mv.y);
                acc[mf][nf][0] = p0; acc[mf][nf][1] = p1;
                acc[mf][nf][2] = p2; acc[mf][nf][3] = p3;
                rs1 += p0 + p1;
                rs2 += p2 + p3;
            }
            rs1 += __shfl_xor_sync(0xffffffffu, rs1, 1);
            rs1 += __shfl_xor_sync(0xffffffffu, rs1, 2);
            rs2 += __shfl_xor_sync(0xffffffffu, rs2, 1);
            rs2 += __shfl_xor_sync(0xffffffffu, rs2, 2);
            l[mf][0] += rs1;
            l[mf][1] += rs2;
        }

        // ---- O += P V, pass-major ----
#pragma unroll
        for (int kf = 0; kf < 4; kf++) {
            uint32_t phi[2][4], plo[2][4];
#pragma unroll
            for (int mf = 0; mf < 2; mf++) {
                split2(acc[mf][2 * kf][0],     acc[mf][2 * kf][1],     phi[mf][0], plo[mf][0]);
                split2(acc[mf][2 * kf][2],     acc[mf][2 * kf][3],     phi[mf][1], plo[mf][1]);
                split2(acc[mf][2 * kf + 1][0], acc[mf][2 * kf + 1][1], phi[mf][2], plo[mf][2]);
                split2(acc[mf][2 * kf + 1][2], acc[mf][2 * kf + 1][3], phi[mf][3], plo[mf][3]);
            }
            uint32_t vhi[4][4], vlo[4][4];
#pragma unroll
            for (int np = 0; np < 4; np++) {
                int row = kf * 16 + (lane & 15);
                int col = (np * 2 + (lane >> 4)) * 8;
                uint32_t ad = sbase + st + (uint32_t)(row * 144 + col * 2);
                ldmatrix_x4_trans(vhi[np][0], vhi[np][1], vhi[np][2], vhi[np][3], ad + F_VH);
                ldmatrix_x4_trans(vlo[np][0], vlo[np][1], vlo[np][2], vlo[np][3], ad + F_VL);
            }
#pragma unroll
            for (int mf = 0; mf < 2; mf++)
#pragma unroll
                for (int np = 0; np < 4; np++) {
                    mma_bf16(o[mf][np * 2],     phi[mf], vhi[np]);
                    mma_bf16(o[mf][np * 2 + 1], phi[mf], vhi[np] + 2);
                }
#pragma unroll
            for (int mf = 0; mf < 2; mf++)
#pragma unroll
                for (int np = 0; np < 4; np++) {
                    mma_bf16(o[mf][np * 2],     phi[mf], vlo[np]);
                    mma_bf16(o[mf][np * 2 + 1], phi[mf], vlo[np] + 2);
                }
#pragma unroll
            for (int mf = 0; mf < 2; mf++)
#pragma unroll
                for (int np = 0; np < 4; np++) {
                    mma_bf16(o[mf][np * 2],     plo[mf], vhi[np]);
                    mma_bf16(o[mf][np * 2 + 1], plo[mf], vhi[np] + 2);
                }
        }
        __syncthreads();
    }

    // ---- epilogue ----
#pragma unroll
    for (int mf = 0; mf < 2; mf++) {
        float inv1 = 1.f / l[mf][0];
        float inv2 = 1.f / l[mf][1];
        int t1 = q0 + qbase + mf * 16 + (lane >> 2);
        int t2 = t1 + 8;
#pragma unroll
        for (int nf = 0; nf < 8; nf++) {
            int d = h * 64 + nf * 8 + (lane & 3) * 2;
            size_t r1 = (size_t)(t1 * 2 + b) * E_DIM + d;
            size_t r2 = (size_t)(t2 * 2 + b) * E_DIM + d;
            uint32_t hw, lw;
            split2(o[mf][nf][0] * inv1, o[mf][nf][1] * inv1, hw, lw);
            *(uint32_t*)(attn_hi + r1) = hw;
            *(uint32_t*)(attn_lo + r1) = lw;
            split2(o[mf][nf][2] * inv2, o[mf][nf][3] * inv2, hw, lw);
            *(uint32_t*)(attn_hi + r2) = hw;
            *(uint32_t*)(attn_lo + r2) = lw;
        }
    }
}

// ===========================================================================
extern "C" void kernel_launch(void* const* d_in, const int* in_sizes, int n_in,
                              void* d_out, int out_size)
{
    const float* x      = (const float*)d_in[0];
    const float* w_in   = (const float*)d_in[1];
    const float* b_in   = (const float*)d_in[2];
    const float* w_out  = (const float*)d_in[3];
    const float* b_out  = (const float*)d_in[4];
    const void*  mask   = d_in[5];
    float* out = (float*)d_out;

    __nv_bfloat16 *x_hi, *x_lo, *win_hi, *win_lo, *wout_hi, *wout_lo;
    __nv_bfloat16 *qkv_hi, *qkv_lo, *attn_hi, *attn_lo;
    cudaGetSymbolAddress((void**)&x_hi, g_x_hi);
    cudaGetSymbolAddress((void**)&x_lo, g_x_lo);
    cudaGetSymbolAddress((void**)&win_hi, g_win_hi);
    cudaGetSymbolAddress((void**)&win_lo, g_win_lo);
    cudaGetSymbolAddress((void**)&wout_hi, g_wout_hi);
    cudaGetSymbolAddress((void**)&wout_lo, g_wout_lo);
    cudaGetSymbolAddress((void**)&qkv_hi, g_qkv_hi);
    cudaGetSymbolAddress((void**)&qkv_lo, g_qkv_lo);
    cudaGetSymbolAddress((void**)&attn_hi, g_attn_hi);
    cudaGetSymbolAddress((void**)&attn_lo, g_attn_lo);

    cudaFuncSetAttribute(gemm_mma2<true>,
                         cudaFuncAttributeMaxDynamicSharedMemorySize, G_TOTAL);
    cudaFuncSetAttribute(gemm_mma2<false>,
                         cudaFuncAttributeMaxDynamicSharedMemorySize, G_TOTAL);
    cudaFuncSetAttribute(flash_mma5,
                         cudaFuncAttributeMaxDynamicSharedMemorySize, F_TOTAL);

    // 0) normalize mask, compact keys, pre-split inputs
    mask_detect_kernel<<<1, 256>>>((const unsigned char*)mask);
    mask_expand_kernel<<<(MROWS + 255) / 256, 256>>>(mask);
    mask_compact_kernel<<<1, 64>>>();
    presplit_kernel<<<(MROWS * E_DIM / 4 + 255) / 256, 256>>>(x, x_hi, x_lo,
                                                              MROWS * E_DIM / 4);
    presplit_kernel<<<(3 * E_DIM * E_DIM / 4 + 255) / 256, 256>>>(
        w_in, win_hi, win_lo, 3 * E_DIM * E_DIM / 4);
    presplit_kernel<<<(E_DIM * E_DIM / 4 + 255) / 256, 256>>>(
        w_out, wout_hi, wout_lo, E_DIM * E_DIM / 4);

    // 1) qkv = x @ W_in^T + b_in  (q pre-scaled by 0.125) -> split bf16
    {
        dim3 grid((3 * E_DIM) / 64, MROWS / 128);
        gemm_mma2<true><<<grid, 256, G_TOTAL>>>(x_hi, x_lo, win_hi, win_lo,
                                                b_in, nullptr,
                                                qkv_hi, qkv_lo, 3 * E_DIM, E_DIM);
    }

    // 2) flash attention (key-compacted) -> split bf16 attn
    {
        dim3 grid(T_DIM / 128, H_DIM, B_DIM);
        flash_mma5<<<grid, 128, F_TOTAL>>>(qkv_hi, qkv_lo, attn_hi, attn_lo);
    }

    // 3) out = attn @ W_out^T + b_out   [4096 x 1024] fp32
    {
        dim3 grid(E_DIM / 64, MROWS / 128);
        gemm_mma2<false><<<grid, 256, G_TOTAL>>>(attn_hi, attn_lo,
                                                 wout_hi, wout_lo,
                                                 b_out, out,
                                                 nullptr, nullptr, E_DIM, 0);
    }
}

// round 10
// speedup vs baseline: 5.3369x; 1.1211x over previous
#include <cuda_runtime.h>
#include <cuda_bf16.h>
#include <cstdint>
#include <cstddef>

#define T_DIM 2048
#define B_DIM 2
#define E_DIM 1024
#define H_DIM 16
#define MROWS (T_DIM * B_DIM)      // 4096
#define K_DIM 1024
#define NEG_INF_F (-1e24f)

// ---------------------------------------------------------------------------
// Scratch (no cudaMalloc allowed)
// ---------------------------------------------------------------------------
__device__ __nv_bfloat16 g_x_hi[(size_t)MROWS * E_DIM];
__device__ __nv_bfloat16 g_x_lo[(size_t)MROWS * E_DIM];
__device__ __nv_bfloat16 g_win_hi[(size_t)3 * E_DIM * E_DIM];
__device__ __nv_bfloat16 g_win_lo[(size_t)3 * E_DIM * E_DIM];
__device__ __nv_bfloat16 g_wout_hi[(size_t)E_DIM * E_DIM];
__device__ __nv_bfloat16 g_wout_lo[(size_t)E_DIM * E_DIM];
// q projection (scaled), row = t*2+b, stride 1024
__device__ __nv_bfloat16 g_q_hi[(size_t)MROWS * E_DIM];
__device__ __nv_bfloat16 g_q_lo[(size_t)MROWS * E_DIM];
// compacted K|V projections: row = b*2048 + compact_j, cols [0,1024)=K, [1024,2048)=V
__device__ __nv_bfloat16 g_kv_hi[(size_t)MROWS * 2 * E_DIM];
__device__ __nv_bfloat16 g_kv_lo[(size_t)MROWS * 2 * E_DIM];
__device__ __nv_bfloat16 g_attn_hi[(size_t)MROWS * E_DIM];
__device__ __nv_bfloat16 g_attn_lo[(size_t)MROWS * E_DIM];
__device__ int g_mask_mode;
__device__ unsigned char g_mask[MROWS];
__device__ int   g_kidx[B_DIM * T_DIM];
__device__ int   g_kcount[B_DIM];
__device__ float g_kmask[B_DIM * T_DIM];

// ===========================================================================
// PTX helpers
// ===========================================================================
__device__ __forceinline__ uint32_t smem_u32(const void* p) {
    uint32_t a;
    asm("{ .reg .u64 t; cvta.to.shared.u64 t, %1; cvt.u32.u64 %0, t; }"
        : "=r"(a) : "l"(p));
    return a;
}
__device__ __forceinline__ void ldmatrix_x4(uint32_t& r0, uint32_t& r1,
                                            uint32_t& r2, uint32_t& r3,
                                            uint32_t addr) {
    asm volatile("ldmatrix.sync.aligned.m8n8.x4.shared.b16 {%0,%1,%2,%3}, [%4];"
                 : "=r"(r0), "=r"(r1), "=r"(r2), "=r"(r3) : "r"(addr));
}
__device__ __forceinline__ void ldmatrix_x4_trans(uint32_t& r0, uint32_t& r1,
                                                  uint32_t& r2, uint32_t& r3,
                                                  uint32_t addr) {
    asm volatile("ldmatrix.sync.aligned.m8n8.x4.trans.shared.b16 {%0,%1,%2,%3}, [%4];"
                 : "=r"(r0), "=r"(r1), "=r"(r2), "=r"(r3) : "r"(addr));
}
__device__ __forceinline__ void mma_bf16(float* d, const uint32_t* a,
                                         const uint32_t* b) {
    asm("mma.sync.aligned.m16n8k16.row.col.f32.bf16.bf16.f32 "
        "{%0,%1,%2,%3}, {%4,%5,%6,%7}, {%8,%9}, {%0,%1,%2,%3};"
        : "+f"(d[0]), "+f"(d[1]), "+f"(d[2]), "+f"(d[3])
        : "r"(a[0]), "r"(a[1]), "r"(a[2]), "r"(a[3]), "r"(b[0]), "r"(b[1]));
}
__device__ __forceinline__ void cp_async16(uint32_t dst, const void* src) {
    asm volatile("cp.async.cg.shared.global [%0], [%1], 16;" :: "r"(dst), "l"(src));
}
__device__ __forceinline__ void cp_commit() {
    asm volatile("cp.async.commit_group;" ::: "memory");
}
template<int N> __device__ __forceinline__ void cp_wait() {
    asm volatile("cp.async.wait_group %0;" :: "n"(N) : "memory");
}

__device__ __forceinline__ void split2(float x, float y,
                                       uint32_t& hi, uint32_t& lo) {
    __nv_bfloat16 hx = __float2bfloat16(x);
    __nv_bfloat16 hy = __float2bfloat16(y);
    __nv_bfloat16 lx = __float2bfloat16(x - __bfloat162float(hx));
    __nv_bfloat16 ly = __float2bfloat16(y - __bfloat162float(hy));
    __nv_bfloat162 hp = __halves2bfloat162(hx, hy);
    __nv_bfloat162 lp = __halves2bfloat162(lx, ly);
    hi = *(uint32_t*)&hp;
    lo = *(uint32_t*)&lp;
}

// ===========================================================================
// Mask normalization / compaction
// ===========================================================================
__global__ void mask_detect_kernel(const unsigned char* __restrict__ m)
{
    __shared__ int s_nz, s_f32;
    if (threadIdx.x == 0) { s_nz = 0; s_f32 = 0; }
    __syncthreads();
    int nz = 0, f32 = 0;
    for (int i = threadIdx.x; i < MROWS; i += 256) {
        unsigned char v = m[i];
        if ((i & 3) != 0 && v != 0) nz = 1;
        if ((i & 3) == 3 && v == 0x3F) f32 = 1;
    }
    if (nz)  atomicOr(&s_nz, 1);
    if (f32) atomicOr(&s_f32, 1);
    __syncthreads();
    if (threadIdx.x == 0)
        g_mask_mode = s_f32 ? 2 : (s_nz ? 0 : 1);
}

__global__ void mask_expand_kernel(const void* __restrict__ m)
{
    int i = blockIdx.x * 256 + threadIdx.x;
    if (i >= MROWS) return;
    int mode = g_mask_mode;
    unsigned char r;
    if (mode == 0)      r = ((const unsigned char*)m)[i] != 0;
    else if (mode == 1) r = ((const int*)m)[i] != 0;
    else                r = ((const float*)m)[i] != 0.0f;
    g_mask[i] = r;
}

__global__ void mask_compact_kernel()
{
    int b = threadIdx.x >> 5;
    int lane = threadIdx.x & 31;
    if (b >= B_DIM) return;
    int base = 0;
    for (int j0 = 0; j0 < T_DIM; j0 += 32) {
        int t = j0 + lane;
        int keep = g_mask[t * B_DIM + b] ? 0 : 1;
        unsigned bal = __ballot_sync(0xffffffffu, keep);
        int pre = __popc(bal & ((1u << lane) - 1));
        if (keep) g_kidx[b * T_DIM + base + pre] = t;
        base += __popc(bal);
    }
    if (lane == 0) g_kcount[b] = base;
    // pad index list to full length; additive pad mask
    for (int j = base + lane; j < T_DIM; j += 32)
        g_kidx[b * T_DIM + j] = 0;
    for (int j = lane; j < T_DIM; j += 32)
        g_kmask[b * T_DIM + j] = (j < base) ? 0.f : NEG_INF_F;
}

// ===========================================================================
// Pre-split fp32 -> bf16 hi/lo
// ===========================================================================
__global__ void presplit_kernel(const float* __restrict__ src,
                                __nv_bfloat16* __restrict__ hi,
                                __nv_bfloat16* __restrict__ lo, int n4)
{
    int i = blockIdx.x * 256 + threadIdx.x;
    if (i >= n4) return;
    float4 v = ((const float4*)src)[i];
    uint32_t h0, l0, h1, l1;
    split2(v.x, v.y, h0, l0);
    split2(v.z, v.w, h1, l1);
    uint2 hh, ll;
    hh.x = h0; hh.y = h1;
    ll.x = l0; ll.y = l1;
    ((uint2*)hi)[i] = hh;
    ((uint2*)lo)[i] = ll;
}

// ===========================================================================
// 2-stage pipelined split-bf16 HMMA GEMM (dense rows)
// ===========================================================================
#define GST   55296
#define G_AH  0
#define G_AL  18432
#define G_BH  36864
#define G_BL  46080
#define G_TOTAL (2 * GST)
#define G_RM  G_TOTAL                 // rowmap (kv variant only)
#define G_TOTAL_KV (G_TOTAL + 512)

template<bool SPLIT_OUT>
__global__ __launch_bounds__(256, 2)
void gemm_mma2(const __nv_bfloat16* __restrict__ Ah,
               const __nv_bfloat16* __restrict__ Al,
               const __nv_bfloat16* __restrict__ Bh,
               const __nv_bfloat16* __restrict__ Bl,
               const float* __restrict__ bias,
               float* __restrict__ C,
               __nv_bfloat16* __restrict__ Ch,
               __nv_bfloat16* __restrict__ Cl,
               int N, int scale_n)
{
    extern __shared__ char sm[];
    uint32_t sbase = smem_u32(sm);
    int tid  = threadIdx.x;
    int lane = tid & 31;
    int wid  = tid >> 5;
    int warp_m = wid & 3;
    int warp_n = wid >> 2;
    int m0 = blockIdx.y * 128;
    int n0 = blockIdx.x * 64;

    float acc[2][4][4];
#pragma unroll
    for (int i = 0; i < 2; i++)
#pragma unroll
        for (int j = 0; j < 4; j++)
#pragma unroll
            for (int c = 0; c < 4; c++) acc[i][j][c] = 0.f;

    auto issue = [&](int k0, uint32_t st) {
#pragma unroll
        for (int it = 0; it < 4; it++) {
            int idx = tid + it * 256;
            int row = idx >> 3, cg = idx & 7;
            size_t g = (size_t)(m0 + row) * K_DIM + k0 + cg * 8;
            uint32_t d = sbase + st + (uint32_t)(row * 144 + cg * 16);
            cp_async16(d + G_AH, Ah + g);
            cp_async16(d + G_AL, Al + g);
        }
#pragma unroll
        for (int it = 0; it < 2; it++) {
            int idx = tid + it * 256;
            int row = idx >> 3, cg = idx & 7;
            size_t g = (size_t)(n0 + row) * K_DIM + k0 + cg * 8;
            uint32_t d = sbase + st + (uint32_t)(row * 144 + cg * 16);
            cp_async16(d + G_BH, Bh + g);
            cp_async16(d + G_BL, Bl + g);
        }
    };

    issue(0, 0);
    cp_commit();

    for (int c = 0; c < 16; c++) {
        uint32_t st = (c & 1) ? GST : 0;
        if (c + 1 < 16) {
            issue((c + 1) * 64, ((c + 1) & 1) ? GST : 0);
            cp_commit();
            cp_wait<1>();
        } else {
            cp_wait<0>();
        }
        __syncthreads();

#pragma unroll
        for (int ks = 0; ks < 4; ks++) {
            uint32_t ahi[2][4], alo[2][4];
#pragma unroll
            for (int mf = 0; mf < 2; mf++) {
                int row = warp_m * 32 + mf * 16 + (lane & 15);
                int col = ks * 16 + (lane >> 4) * 8;
                uint32_t ad = sbase + st + (uint32_t)(row * 144 + col * 2);
                ldmatrix_x4(ahi[mf][0], ahi[mf][1], ahi[mf][2], ahi[mf][3], ad + G_AH);
                ldmatrix_x4(alo[mf][0], alo[mf][1], alo[mf][2], alo[mf][3], ad + G_AL);
            }
            uint32_t bhi[4][2], blo[4][2];
#pragma unroll
            for (int np = 0; np < 2; np++) {
                int row = warp_n * 32 + (np * 2 + (lane >> 4)) * 8 + (lane & 7);
                int col = ks * 16 + ((lane >> 3) & 1) * 8;
                uint32_t ad = sbase + st + (uint32_t)(row * 144 + col * 2);
                uint32_t r0, r1, r2, r3;
                ldmatrix_x4(r0, r1, r2, r3, ad + G_BH);
                bhi[np * 2][0] = r0; bhi[np * 2][1] = r1;
                bhi[np * 2 + 1][0] = r2; bhi[np * 2 + 1][1] = r3;
                ldmatrix_x4(r0, r1, r2, r3, ad + G_BL);
                blo[np * 2][0] = r0; blo[np * 2][1] = r1;
                blo[np * 2 + 1][0] = r2; blo[np * 2 + 1][1] = r3;
            }
#pragma unroll
            for (int mf = 0; mf < 2; mf++)
#pragma unroll
                for (int nf = 0; nf < 4; nf++)
                    mma_bf16(acc[mf][nf], ahi[mf], bhi[nf]);
#pragma unroll
            for (int mf = 0; mf < 2; mf++)
#pragma unroll
                for (int nf = 0; nf < 4; nf++)
                    mma_bf16(acc[mf][nf], ahi[mf], blo[nf]);
#pragma unroll
            for (int mf = 0; mf < 2; mf++)
#pragma unroll
                for (int nf = 0; nf < 4; nf++)
                    mma_bf16(acc[mf][nf], alo[mf], bhi[nf]);
        }
        __syncthreads();
    }

#pragma unroll
    for (int mf = 0; mf < 2; mf++) {
#pragma unroll
        for (int nf = 0; nf < 4; nf++) {
            int row = m0 + warp_m * 32 + mf * 16 + (lane >> 2);
            int col = n0 + warp_n * 32 + nf * 8 + (lane & 3) * 2;
            float sc = (col < scale_n) ? 0.125f : 1.0f;
            float b0 = bias[col], b1 = bias[col + 1];
            float d0 = (acc[mf][nf][0] + b0) * sc;
            float d1 = (acc[mf][nf][1] + b1) * sc;
            float d2 = (acc[mf][nf][2] + b0) * sc;
            float d3 = (acc[mf][nf][3] + b1) * sc;
            if (SPLIT_OUT) {
                uint32_t hw, lw;
                split2(d0, d1, hw, lw);
                *(uint32_t*)(Ch + (size_t)row * N + col) = hw;
                *(uint32_t*)(Cl + (size_t)row * N + col) = lw;
                split2(d2, d3, hw, lw);
                *(uint32_t*)(Ch + (size_t)(row + 8) * N + col) = hw;
                *(uint32_t*)(Cl + (size_t)(row + 8) * N + col) = lw;
            } else {
                C[(size_t)row * N + col]           = d0;
                C[(size_t)row * N + col + 1]       = d1;
                C[(size_t)(row + 8) * N + col]     = d2;
                C[(size_t)(row + 8) * N + col + 1] = d3;
            }
        }
    }
}

// ===========================================================================
// KV GEMM: row-gathered A over compacted unmasked keys; early-exit past count.
// Output g_kv_* at row m0+..., N=2048 (K cols 0..1023, V cols 1024..2047).
// ===========================================================================
__global__ __launch_bounds__(256, 2)
void gemm_kv(const __nv_bfloat16* __restrict__ Ah,
             const __nv_bfloat16* __restrict__ Al,
             const __nv_bfloat16* __restrict__ Bh,   // win rows 1024..3071
             const __nv_bfloat16* __restrict__ Bl,
             const float* __restrict__ bias,         // b_in + 1024
             __nv_bfloat16* __restrict__ Ch,
             __nv_bfloat16* __restrict__ Cl)
{
    extern __shared__ char sm[];
    uint32_t sbase = smem_u32(sm);
    int* s_row = (int*)(sm + G_RM);
    int tid  = threadIdx.x;
    int lane = tid & 31;
    int wid  = tid >> 5;
    int warp_m = wid & 3;
    int warp_n = wid >> 2;
    int m0 = blockIdx.y * 128;
    int n0 = blockIdx.x * 64;
    const int N = 2 * E_DIM;

    int b = (m0 >= T_DIM) ? 1 : 0;
    int j0 = m0 - b * T_DIM;
    int cnt = g_kcount[b];
    if (j0 >= ((cnt + 63) & ~63)) return;   // tile entirely beyond padded count

    // stage gather row map (x row = t*2 + b)
    if (tid < 128)
        s_row[tid] = g_kidx[b * T_DIM + j0 + tid] * 2 + b;
    __syncthreads();

    float acc[2][4][4];
#pragma unroll
    for (int i = 0; i < 2; i++)
#pragma unroll
        for (int j = 0; j < 4; j++)
#pragma unroll
            for (int c = 0; c < 4; c++) acc[i][j][c] = 0.f;

    auto issue = [&](int k0, uint32_t st) {
#pragma unroll
        for (int it = 0; it < 4; it++) {
            int idx = tid + it * 256;
            int row = idx >> 3, cg = idx & 7;
            size_t g = (size_t)s_row[row] * K_DIM + k0 + cg * 8;
            uint32_t d = sbase + st + (uint32_t)(row * 144 + cg * 16);
            cp_async16(d + G_AH, Ah + g);
            cp_async16(d + G_AL, Al + g);
        }
#pragma unroll
        for (int it = 0; it < 2; it++) {
            int idx = tid + it * 256;
            int row = idx >> 3, cg = idx & 7;
            size_t g = (size_t)(n0 + row) * K_DIM + k0 + cg * 8;
            uint32_t d = sbase + st + (uint32_t)(row * 144 + cg * 16);
            cp_async16(d + G_BH, Bh + g);
            cp_async16(d + G_BL, Bl + g);
        }
    };

    issue(0, 0);
    cp_commit();

    for (int c = 0; c < 16; c++) {
        uint32_t st = (c & 1) ? GST : 0;
        if (c + 1 < 16) {
            issue((c + 1) * 64, ((c + 1) & 1) ? GST : 0);
            cp_commit();
            cp_wait<1>();
        } else {
            cp_wait<0>();
        }
        __syncthreads();

#pragma unroll
        for (int ks = 0; ks < 4; ks++) {
            uint32_t ahi[2][4], alo[2][4];
#pragma unroll
            for (int mf = 0; mf < 2; mf++) {
                int row = warp_m * 32 + mf * 16 + (lane & 15);
                int col = ks * 16 + (lane >> 4) * 8;
                uint32_t ad = sbase + st + (uint32_t)(row * 144 + col * 2);
                ldmatrix_x4(ahi[mf][0], ahi[mf][1], ahi[mf][2], ahi[mf][3], ad + G_AH);
                ldmatrix_x4(alo[mf][0], alo[mf][1], alo[mf][2], alo[mf][3], ad + G_AL);
            }
            uint32_t bhi[4][2], blo[4][2];
#pragma unroll
            for (int np = 0; np < 2; np++) {
                int row = warp_n * 32 + (np * 2 + (lane >> 4)) * 8 + (lane & 7);
                int col = ks * 16 + ((lane >> 3) & 1) * 8;
                uint32_t ad = sbase + st + (uint32_t)(row * 144 + col * 2);
                uint32_t r0, r1, r2, r3;
                ldmatrix_x4(r0, r1, r2, r3, ad + G_BH);
                bhi[np * 2][0] = r0; bhi[np * 2][1] = r1;
                bhi[np * 2 + 1][0] = r2; bhi[np * 2 + 1][1] = r3;
                ldmatrix_x4(r0, r1, r2, r3, ad + G_BL);
                blo[np * 2][0] = r0; blo[np * 2][1] = r1;
                blo[np * 2 + 1][0] = r2; blo[np * 2 + 1][1] = r3;
            }
#pragma unroll
            for (int mf = 0; mf < 2; mf++)
#pragma unroll
                for (int nf = 0; nf < 4; nf++)
                    mma_bf16(acc[mf][nf], ahi[mf], bhi[nf]);
#pragma unroll
            for (int mf = 0; mf < 2; mf++)
#pragma unroll
                for (int nf = 0; nf < 4; nf++)
                    mma_bf16(acc[mf][nf], ahi[mf], blo[nf]);
#pragma unroll
            for (int mf = 0; mf < 2; mf++)
#pragma unroll
                for (int nf = 0; nf < 4; nf++)
                    mma_bf16(acc[mf][nf], alo[mf], bhi[nf]);
        }
        __syncthreads();
    }

#pragma unroll
    for (int mf = 0; mf < 2; mf++) {
#pragma unroll
        for (int nf = 0; nf < 4; nf++) {
            int row = m0 + warp_m * 32 + mf * 16 + (lane >> 2);
            int col = n0 + warp_n * 32 + nf * 8 + (lane & 3) * 2;
            float b0 = bias[col], b1 = bias[col + 1];
            float d0 = acc[mf][nf][0] + b0;
            float d1 = acc[mf][nf][1] + b1;
            float d2 = acc[mf][nf][2] + b0;
            float d3 = acc[mf][nf][3] + b1;
            uint32_t hw, lw;
            split2(d0, d1, hw, lw);
            *(uint32_t*)(Ch + (size_t)row * N + col) = hw;
            *(uint32_t*)(Cl + (size_t)row * N + col) = lw;
            split2(d2, d3, hw, lw);
            *(uint32_t*)(Ch + (size_t)(row + 8) * N + col) = hw;
            *(uint32_t*)(Cl + (size_t)(row + 8) * N + col) = lw;
        }
    }
}

// ===========================================================================
// Flash attention v6: key-compacted with CONTIGUOUS K/V loads from g_kv.
// ===========================================================================
#define F_QH   0
#define F_QL   18432
#define F_ST0  36864
#define F_ST1  73728
#define F_KH   0
#define F_KL   9216
#define F_VH   18432
#define F_VL   27648
#define F_MSK0 110592
#define F_MSK1 110848
#define F_TOTAL 111104

__global__ __launch_bounds__(128, 2)
void flash_mma6(const __nv_bfloat16* __restrict__ q_hi,
                const __nv_bfloat16* __restrict__ q_lo,
                const __nv_bfloat16* __restrict__ kv_hi,
                const __nv_bfloat16* __restrict__ kv_lo,
                __nv_bfloat16* __restrict__ attn_hi,
                __nv_bfloat16* __restrict__ attn_lo)
{
    extern __shared__ char sm[];
    uint32_t sbase = smem_u32(sm);
    float* msk0 = (float*)(sm + F_MSK0);
    float* msk1 = (float*)(sm + F_MSK1);
    int tid = threadIdx.x;
    int lane = tid & 31;
    int w = tid >> 5;
    int b = blockIdx.z;
    int h = blockIdx.y;
    int q0 = blockIdx.x * 128;
    int qbase = w * 32;

    int cnt = g_kcount[b];
    int ntiles = (cnt + 63) >> 6;

#pragma unroll
    for (int it = 0; it < 8; it++) {
        int idx = tid + it * 128;
        int row = idx >> 3, cg = idx & 7;
        size_t g = (size_t)((q0 + row) * 2 + b) * E_DIM + h * 64 + cg * 8;
        uint32_t d = sbase + (uint32_t)(row * 144 + cg * 16);
        cp_async16(d + F_QH, q_hi + g);
        cp_async16(d + F_QL, q_lo + g);
    }
    cp_commit();

    auto issue_kv = [&](int s0, uint32_t st) {
#pragma unroll
        for (int it = 0; it < 4; it++) {
            int idx = tid + it * 128;
            int row = idx >> 3, cg = idx & 7;
            size_t g = (size_t)(b * T_DIM + s0 + row) * (2 * E_DIM) + h * 64 + cg * 8;
            uint32_t d = sbase + st + (uint32_t)(row * 144 + cg * 16);
            cp_async16(d + F_KH, kv_hi + g);
            cp_async16(d + F_KL, kv_lo + g);
            cp_async16(d + F_VH, kv_hi + g + E_DIM);
            cp_async16(d + F_VL, kv_lo + g + E_DIM);
        }
    };

    issue_kv(0, F_ST0);
    if (tid < 64)
        msk0[tid] = g_kmask[b * T_DIM + tid];
    cp_commit();

    float l[2][2];
    l[0][0] = l[0][1] = l[1][0] = l[1][1] = 0.f;
    float o[2][8][4];
#pragma unroll
    for (int mf = 0; mf < 2; mf++)
#pragma unroll
        for (int nf = 0; nf < 8; nf++)
#pragma unroll
            for (int c = 0; c < 4; c++) o[mf][nf][c] = 0.f;

    for (int c = 0; c < ntiles; c++) {
        uint32_t st = (c & 1) ? F_ST1 : F_ST0;
        float* mk = (c & 1) ? msk1 : msk0;
        if (c + 1 < ntiles) {
            issue_kv((c + 1) * 64, ((c + 1) & 1) ? F_ST1 : F_ST0);
            float* mkn = ((c + 1) & 1) ? msk1 : msk0;
            if (tid < 64)
                mkn[tid] = g_kmask[b * T_DIM + (c + 1) * 64 + tid];
            cp_commit();
            cp_wait<1>();
        } else {
            cp_wait<0>();
        }
        __syncthreads();

        // ---- S = Q K^T, pass-major ----
        float acc[2][8][4];
#pragma unroll
        for (int mf = 0; mf < 2; mf++)
#pragma unroll
            for (int nf = 0; nf < 8; nf++)
#pragma unroll
                for (int cc = 0; cc < 4; cc++) acc[mf][nf][cc] = 0.f;

#pragma unroll
        for (int kf = 0; kf < 4; kf++) {
            uint32_t qhi[2][4], qlo[2][4];
#pragma unroll
            for (int mf = 0; mf < 2; mf++) {
                int row = qbase + mf * 16 + (lane & 15);
                int col = kf * 16 + (lane >> 4) * 8;
                uint32_t ad = sbase + (uint32_t)(row * 144 + col * 2);
                ldmatrix_x4(qhi[mf][0], qhi[mf][1], qhi[mf][2], qhi[mf][3], ad + F_QH);
                ldmatrix_x4(qlo[mf][0], qlo[mf][1], qlo[mf][2], qlo[mf][3], ad + F_QL);
            }
            uint32_t khi[4][4], klo[4][4];
#pragma unroll
            for (int np = 0; np < 4; np++) {
                int row = (np * 2 + (lane >> 4)) * 8 + (lane & 7);
                int col = kf * 16 + ((lane >> 3) & 1) * 8;
                uint32_t ad = sbase + st + (uint32_t)(row * 144 + col * 2);
                ldmatrix_x4(khi[np][0], khi[np][1], khi[np][2], khi[np][3], ad + F_KH);
                ldmatrix_x4(klo[np][0], klo[np][1], klo[np][2], klo[np][3], ad + F_KL);
            }
#pragma unroll
            for (int mf = 0; mf < 2; mf++)
#pragma unroll
                for (int np = 0; np < 4; np++) {
                    mma_bf16(acc[mf][np * 2],     qhi[mf], khi[np]);
                    mma_bf16(acc[mf][np * 2 + 1], qhi[mf], khi[np] + 2);
                }
#pragma unroll
            for (int mf = 0; mf < 2; mf++)
#pragma unroll
                for (int np = 0; np < 4; np++) {
                    mma_bf16(acc[mf][np * 2],     qhi[mf], klo[np]);
                    mma_bf16(acc[mf][np * 2 + 1], qhi[mf], klo[np] + 2);
                }
#pragma unroll
            for (int mf = 0; mf < 2; mf++)
#pragma unroll
                for (int np = 0; np < 4; np++) {
                    mma_bf16(acc[mf][np * 2],     qlo[mf], khi[np]);
                    mma_bf16(acc[mf][np * 2 + 1], qlo[mf], khi[np] + 2);
                }
        }

        // ---- pad-mask + exp (fixed reference m = 0) ----
#pragma unroll
        for (int mf = 0; mf < 2; mf++) {
            float rs1 = 0.f, rs2 = 0.f;
#pragma unroll
            for (int nf = 0; nf < 8; nf++) {
                float2 mv = *(float2*)&mk[nf * 8 + (lane & 3) * 2];
                float p0 = __expf(acc[mf][nf][0] + mv.x);
                float p1 = __expf(acc[mf][nf][1] + mv.y);
                float p2 = __expf(acc[mf][nf][2] + mv.x);
                float p3 = __expf(acc[mf][nf][3] + mv.y);
                acc[mf][nf][0] = p0; acc[mf][nf][1] = p1;
                acc[mf][nf][2] = p2; acc[mf][nf][3] = p3;
                rs1 += p0 + p1;
                rs2 += p2 + p3;
            }
            rs1 += __shfl_xor_sync(0xffffffffu, rs1, 1);
            rs1 += __shfl_xor_sync(0xffffffffu, rs1, 2);
            rs2 += __shfl_xor_sync(0xffffffffu, rs2, 1);
            rs2 += __shfl_xor_sync(0xffffffffu, rs2, 2);
            l[mf][0] += rs1;
            l[mf][1] += rs2;
        }

        // ---- O += P V, pass-major ----
#pragma unroll
        for (int kf = 0; kf < 4; kf++) {
            uint32_t phi[2][4], plo[2][4];
#pragma unroll
            for (int mf = 0; mf < 2; mf++) {
                split2(acc[mf][2 * kf][0],     acc[mf][2 * kf][1],     phi[mf][0], plo[mf][0]);
                split2(acc[mf][2 * kf][2],     acc[mf][2 * kf][3],     phi[mf][1], plo[mf][1]);
                split2(acc[mf][2 * kf + 1][0], acc[mf][2 * kf + 1][1], phi[mf][2], plo[mf][2]);
                split2(acc[mf][2 * kf + 1][2], acc[mf][2 * kf + 1][3], phi[mf][3], plo[mf][3]);
            }
            uint32_t vhi[4][4], vlo[4][4];
#pragma unroll
            for (int np = 0; np < 4; np++) {
                int row = kf * 16 + (lane & 15);
                int col = (np * 2 + (lane >> 4)) * 8;
                uint32_t ad = sbase + st + (uint32_t)(row * 144 + col * 2);
                ldmatrix_x4_trans(vhi[np][0], vhi[np][1], vhi[np][2], vhi[np][3], ad + F_VH);
                ldmatrix_x4_trans(vlo[np][0], vlo[np][1], vlo[np][2], vlo[np][3], ad + F_VL);
            }
#pragma unroll
            for (int mf = 0; mf < 2; mf++)
#pragma unroll
                for (int np = 0; np < 4; np++) {
                    mma_bf16(o[mf][np * 2],     phi[mf], vhi[np]);
                    mma_bf16(o[mf][np * 2 + 1], phi[mf], vhi[np] + 2);
                }
#pragma unroll
            for (int mf = 0; mf < 2; mf++)
#pragma unroll
                for (int np = 0; np < 4; np++) {
                    mma_bf16(o[mf][np * 2],     phi[mf], vlo[np]);
                    mma_bf16(o[mf][np * 2 + 1], phi[mf], vlo[np] + 2);
                }
#pragma unroll
            for (int mf = 0; mf < 2; mf++)
#pragma unroll
                for (int np = 0; np < 4; np++) {
                    mma_bf16(o[mf][np * 2],     plo[mf], vhi[np]);
                    mma_bf16(o[mf][np * 2 + 1], plo[mf], vhi[np] + 2);
                }
        }
        __syncthreads();
    }

    // ---- epilogue ----
#pragma unroll
    for (int mf = 0; mf < 2; mf++) {
        float inv1 = 1.f / l[mf][0];
        float inv2 = 1.f / l[mf][1];
        int t1 = q0 + qbase + mf * 16 + (lane >> 2);
        int t2 = t1 + 8;
#pragma unroll
        for (int nf = 0; nf < 8; nf++) {
            int d = h * 64 + nf * 8 + (lane & 3) * 2;
            size_t r1 = (size_t)(t1 * 2 + b) * E_DIM + d;
            size_t r2 = (size_t)(t2 * 2 + b) * E_DIM + d;
            uint32_t hw, lw;
            split2(o[mf][nf][0] * inv1, o[mf][nf][1] * inv1, hw, lw);
            *(uint32_t*)(attn_hi + r1) = hw;
            *(uint32_t*)(attn_lo + r1) = lw;
            split2(o[mf][nf][2] * inv2, o[mf][nf][3] * inv2, hw, lw);
            *(uint32_t*)(attn_hi + r2) = hw;
            *(uint32_t*)(attn_lo + r2) = lw;
        }
    }
}

// ===========================================================================
extern "C" void kernel_launch(void* const* d_in, const int* in_sizes, int n_in,
                              void* d_out, int out_size)
{
    const float* x      = (const float*)d_in[0];
    const float* w_in   = (const float*)d_in[1];
    const float* b_in   = (const float*)d_in[2];
    const float* w_out  = (const float*)d_in[3];
    const float* b_out  = (const float*)d_in[4];
    const void*  mask   = d_in[5];
    float* out = (float*)d_out;

    __nv_bfloat16 *x_hi, *x_lo, *win_hi, *win_lo, *wout_hi, *wout_lo;
    __nv_bfloat16 *q_hi, *q_lo, *kv_hi, *kv_lo, *attn_hi, *attn_lo;
    cudaGetSymbolAddress((void**)&x_hi, g_x_hi);
    cudaGetSymbolAddress((void**)&x_lo, g_x_lo);
    cudaGetSymbolAddress((void**)&win_hi, g_win_hi);
    cudaGetSymbolAddress((void**)&win_lo, g_win_lo);
    cudaGetSymbolAddress((void**)&wout_hi, g_wout_hi);
    cudaGetSymbolAddress((void**)&wout_lo, g_wout_lo);
    cudaGetSymbolAddress((void**)&q_hi, g_q_hi);
    cudaGetSymbolAddress((void**)&q_lo, g_q_lo);
    cudaGetSymbolAddress((void**)&kv_hi, g_kv_hi);
    cudaGetSymbolAddress((void**)&kv_lo, g_kv_lo);
    cudaGetSymbolAddress((void**)&attn_hi, g_attn_hi);
    cudaGetSymbolAddress((void**)&attn_lo, g_attn_lo);

    cudaFuncSetAttribute(gemm_mma2<true>,
                         cudaFuncAttributeMaxDynamicSharedMemorySize, G_TOTAL);
    cudaFuncSetAttribute(gemm_mma2<false>,
                         cudaFuncAttributeMaxDynamicSharedMemorySize, G_TOTAL);
    cudaFuncSetAttribute(gemm_kv,
                         cudaFuncAttributeMaxDynamicSharedMemorySize, G_TOTAL_KV);
    cudaFuncSetAttribute(flash_mma6,
                         cudaFuncAttributeMaxDynamicSharedMemorySize, F_TOTAL);

    // 0) normalize mask, compact keys, pre-split inputs
    mask_detect_kernel<<<1, 256>>>((const unsigned char*)mask);
    mask_expand_kernel<<<(MROWS + 255) / 256, 256>>>(mask);
    mask_compact_kernel<<<1, 64>>>();
    presplit_kernel<<<(MROWS * E_DIM / 4 + 255) / 256, 256>>>(x, x_hi, x_lo,
                                                              MROWS * E_DIM / 4);
    presplit_kernel<<<(3 * E_DIM * E_DIM / 4 + 255) / 256, 256>>>(
        w_in, win_hi, win_lo, 3 * E_DIM * E_DIM / 4);
    presplit_kernel<<<(E_DIM * E_DIM / 4 + 255) / 256, 256>>>(
        w_out, wout_hi, wout_lo, E_DIM * E_DIM / 4);

    // 1a) q = x @ Wq^T + bq, scaled 0.125 -> split bf16 (full rows)
    {
        dim3 grid(E_DIM / 64, MROWS / 128);
        gemm_mma2<true><<<grid, 256, G_TOTAL>>>(x_hi, x_lo, win_hi, win_lo,
                                                b_in, nullptr,
                                                q_hi, q_lo, E_DIM, E_DIM);
    }
    // 1b) k|v = gathered x @ Wkv^T + bkv -> compacted split bf16
    {
        dim3 grid((2 * E_DIM) / 64, MROWS / 128);
        gemm_kv<<<grid, 256, G_TOTAL_KV>>>(x_hi, x_lo,
                                           win_hi + (size_t)E_DIM * K_DIM,
                                           win_lo + (size_t)E_DIM * K_DIM,
                                           b_in + E_DIM,
                                           kv_hi, kv_lo);
    }

    // 2) flash attention (compacted, contiguous K/V) -> split bf16 attn
    {
        dim3 grid(T_DIM / 128, H_DIM, B_DIM);
        flash_mma6<<<grid, 128, F_TOTAL>>>(q_hi, q_lo, kv_hi, kv_lo,
                                           attn_hi, attn_lo);
    }

    // 3) out = attn @ W_out^T + b_out   [4096 x 1024] fp32
    {
        dim3 grid(E_DIM / 64, MROWS / 128);
        gemm_mma2<false><<<grid, 256, G_TOTAL>>>(attn_hi, attn_lo,
                                                 wout_hi, wout_lo,
                                                 b_out, out,
                                                 nullptr, nullptr, E_DIM, 0);
    }
}